// round 7
// baseline (speedup 1.0000x reference)
#include <cuda_runtime.h>
#include <math.h>

// Problem constants
#define Bsz 2
#define Ssz 2048
#define Dsz 1024
#define Hsz 16
#define DKsz 64
#define BHsz (Bsz * Hsz)

// Fused-attention tiling
#define ROWS 16        // query rows per block
#define CH   256       // K/V chunk rows
#define SC_STRIDE 2052 // scores smem stride in words (2048 + 4, bank-skewed)

// Scratch (allocation-free rule: __device__ globals)
__device__ float g_Q[(long)Bsz * Ssz * Dsz];
__device__ float g_K[(long)Bsz * Ssz * Dsz];
__device__ float g_V[(long)Bsz * Ssz * Dsz];
__device__ float g_X[(long)Bsz * Ssz * Dsz];

__device__ __forceinline__ unsigned f2tf(float f) {
    unsigned u;
    asm("cvt.rna.tf32.f32 %0, %1;" : "=r"(u) : "f"(f));
    return u;
}

__device__ __forceinline__ void mma_tf32(float c[4], unsigned a0, unsigned a1,
                                         unsigned a2, unsigned a3,
                                         unsigned b0, unsigned b1) {
    asm volatile(
        "mma.sync.aligned.m16n8k8.row.col.f32.tf32.tf32.f32 "
        "{%0,%1,%2,%3}, {%4,%5,%6,%7}, {%8,%9}, {%0,%1,%2,%3};"
        : "+f"(c[0]), "+f"(c[1]), "+f"(c[2]), "+f"(c[3])
        : "r"(a0), "r"(a1), "r"(a2), "r"(a3), "r"(b0), "r"(b1));
}

// ---------------------------------------------------------------------------
// tf32 tensor-core GEMM for projections: C = A[M,K] @ B[K,N]
// Block tile 128x64, BK=32, 256 threads (8 warps, each 32x32 warp tile).
// ---------------------------------------------------------------------------
__device__ __forceinline__ void gemm_mma_nn(const float* __restrict__ A, int lda,
                                            const float* __restrict__ B, int ldb,
                                            float* __restrict__ C, int ldc,
                                            int K) {
    __shared__ __align__(16) unsigned As[128][36];
    __shared__ __align__(16) unsigned Bs[32][72];

    const int t    = threadIdx.x;
    const int lane = t & 31;
    const int warp = t >> 5;
    const int wm   = (warp & 3) * 32;
    const int wn   = (warp >> 2) * 32;
    const int g    = lane >> 2;
    const int tg   = lane & 3;

    const int row0 = blockIdx.y * 128;
    const int col0 = blockIdx.x * 64;

    float c[2][4][4];
#pragma unroll
    for (int mi = 0; mi < 2; mi++)
#pragma unroll
        for (int ni = 0; ni < 4; ni++)
#pragma unroll
            for (int r = 0; r < 4; r++) c[mi][ni][r] = 0.0f;

    for (int k0 = 0; k0 < K; k0 += 32) {
#pragma unroll
        for (int i = 0; i < 4; i++) {
            const int fidx = t + i * 256;
            const int r  = fidx >> 3;
            const int c4 = (fidx & 7) << 2;
            float4 v = *reinterpret_cast<const float4*>(
                A + (long)(row0 + r) * lda + k0 + c4);
            uint4 u = {f2tf(v.x), f2tf(v.y), f2tf(v.z), f2tf(v.w)};
            *reinterpret_cast<uint4*>(&As[r][c4]) = u;
        }
#pragma unroll
        for (int i = 0; i < 2; i++) {
            const int fidx = t + i * 256;
            const int r  = fidx >> 4;
            const int c4 = (fidx & 15) << 2;
            float4 v = *reinterpret_cast<const float4*>(
                B + (long)(k0 + r) * ldb + col0 + c4);
            uint4 u = {f2tf(v.x), f2tf(v.y), f2tf(v.z), f2tf(v.w)};
            *reinterpret_cast<uint4*>(&Bs[r][c4]) = u;
        }
        __syncthreads();

#pragma unroll
        for (int ks = 0; ks < 4; ks++) {
            const int k8 = ks * 8;
            unsigned a[2][4];
#pragma unroll
            for (int mi = 0; mi < 2; mi++) {
                const int mb = wm + mi * 16;
                a[mi][0] = As[mb + g][k8 + tg];
                a[mi][1] = As[mb + g + 8][k8 + tg];
                a[mi][2] = As[mb + g][k8 + tg + 4];
                a[mi][3] = As[mb + g + 8][k8 + tg + 4];
            }
#pragma unroll
            for (int ni = 0; ni < 4; ni++) {
                const int nb = wn + ni * 8;
                unsigned b0 = Bs[k8 + tg][nb + g];
                unsigned b1 = Bs[k8 + tg + 4][nb + g];
#pragma unroll
                for (int mi = 0; mi < 2; mi++)
                    mma_tf32(c[mi][ni], a[mi][0], a[mi][1], a[mi][2], a[mi][3],
                             b0, b1);
            }
        }
        __syncthreads();
    }

#pragma unroll
    for (int mi = 0; mi < 2; mi++) {
#pragma unroll
        for (int ni = 0; ni < 4; ni++) {
            const int row = row0 + wm + mi * 16 + g;
            const int col = col0 + wn + ni * 8 + tg * 2;
            float2 v0 = {c[mi][ni][0], c[mi][ni][1]};
            *reinterpret_cast<float2*>(C + (long)row * ldc + col) = v0;
            float2 v1 = {c[mi][ni][2], c[mi][ni][3]};
            *reinterpret_cast<float2*>(C + (long)(row + 8) * ldc + col) = v1;
        }
    }
}

__global__ void __launch_bounds__(256)
proj_kernel(const float* __restrict__ X,
            const float* __restrict__ W,
            float* __restrict__ Y) {
    gemm_mma_nn(X, Dsz, W, Dsz, Y, Dsz, Dsz);
}

// ---------------------------------------------------------------------------
// Fused attention: scores -> masked softmax -> attn write -> P@V
// Block: 16 query rows x one (b,h). Dynamic smem:
//   scores: float [16][SC_STRIDE]                   131328 B
//   KV chunk: K as [256][68] tf32 / V as [256][72]   73728 B
//   Qs: [16][68] tf32                                 4352 B
// Total 209408 B. grid (Ssz/ROWS=128, BHsz=32), 256 threads.
// ---------------------------------------------------------------------------
#define SM_SCORES 0
#define SM_KV     (ROWS * SC_STRIDE * 4)            // 131328
#define SM_Q      (SM_KV + CH * 72 * 4)             // 131328 + 73728
#define SM_TOTAL  (SM_Q + ROWS * 68 * 4)            // + 4352 = 209408

__global__ void __launch_bounds__(256)
attn_fused_kernel(const int* __restrict__ mask, float* __restrict__ attn) {
    extern __shared__ __align__(16) char sm[];
    float*    scores = reinterpret_cast<float*>(sm + SM_SCORES);
    unsigned* Ps     = reinterpret_cast<unsigned*>(sm + SM_SCORES);
    unsigned* KV     = reinterpret_cast<unsigned*>(sm + SM_KV);
    unsigned* Qs     = reinterpret_cast<unsigned*>(sm + SM_Q);

    const int t    = threadIdx.x;
    const int lane = t & 31;
    const int warp = t >> 5;
    const int g    = lane >> 2;
    const int tg   = lane & 3;

    const int z = blockIdx.y;          // b*H + h
    const int b = z >> 4, h = z & 15;
    const int row0 = blockIdx.x * ROWS;

    const float* Qg = g_Q + (long)b * Ssz * Dsz + h * DKsz;
    const float* Kg = g_K + (long)b * Ssz * Dsz + h * DKsz;
    const float* Vg = g_V + (long)b * Ssz * Dsz + h * DKsz;

    // Stage Q tile [16 x 64] as tf32
    {
        const int r  = t >> 4;
        const int c4 = (t & 15) << 2;
        float4 v = *reinterpret_cast<const float4*>(
            Qg + (long)(row0 + r) * Dsz + c4);
        uint4 u = {f2tf(v.x), f2tf(v.y), f2tf(v.z), f2tf(v.w)};
        *reinterpret_cast<uint4*>(&Qs[r * 68 + c4]) = u;
    }

    // ===== Phase 1: scores = (1/8) Q K^T into smem =====
    for (int nc = 0; nc < Ssz / CH; nc++) {
        // Stage K chunk [CH x 64] as tf32, layout [n][k] stride 68
#pragma unroll
        for (int i = 0; i < 16; i++) {
            const int idx = t + i * 256;
            const int r  = idx >> 4;
            const int c4 = (idx & 15) << 2;
            float4 v = *reinterpret_cast<const float4*>(
                Kg + (long)(nc * CH + r) * Dsz + c4);
            uint4 u = {f2tf(v.x), f2tf(v.y), f2tf(v.z), f2tf(v.w)};
            *reinterpret_cast<uint4*>(&KV[r * 68 + c4]) = u;
        }
        __syncthreads();

        float c[4][4];
#pragma unroll
        for (int ni = 0; ni < 4; ni++)
#pragma unroll
            for (int r = 0; r < 4; r++) c[ni][r] = 0.0f;

#pragma unroll
        for (int ks = 0; ks < 8; ks++) {
            const int k8 = ks * 8;
            unsigned a0 = Qs[g * 68 + k8 + tg];
            unsigned a1 = Qs[(g + 8) * 68 + k8 + tg];
            unsigned a2 = Qs[g * 68 + k8 + tg + 4];
            unsigned a3 = Qs[(g + 8) * 68 + k8 + tg + 4];
#pragma unroll
            for (int ni = 0; ni < 4; ni++) {
                const int nb = warp * 32 + ni * 8;
                unsigned b0 = KV[(nb + g) * 68 + k8 + tg];
                unsigned b1 = KV[(nb + g) * 68 + k8 + tg + 4];
                mma_tf32(c[ni], a0, a1, a2, a3, b0, b1);
            }
        }
        // Write scaled scores to smem
#pragma unroll
        for (int ni = 0; ni < 4; ni++) {
            const int col = nc * CH + warp * 32 + ni * 8 + tg * 2;
            scores[g * SC_STRIDE + col]           = c[ni][0] * 0.125f;
            scores[g * SC_STRIDE + col + 1]       = c[ni][1] * 0.125f;
            scores[(g + 8) * SC_STRIDE + col]     = c[ni][2] * 0.125f;
            scores[(g + 8) * SC_STRIDE + col + 1] = c[ni][3] * 0.125f;
        }
        __syncthreads();
    }

    // ===== Phase 2: masked softmax, write attn, leave tf32 P in smem =====
    {
        const int row = t >> 4;
        const int il  = t & 15;
        float* srow = scores + row * SC_STRIDE;
        const int* mp = mask + ((long)b * Ssz + row0 + row) * Ssz;
        float* arow = attn + ((long)z * Ssz + row0 + row) * Ssz;

        float mx = -3.0e38f;
#pragma unroll 8
        for (int j = 0; j < Ssz / 16; j++) {
            const int k = il + (j << 4);
            float v = srow[k];
            if (mp[k] == 0) v = -1e9f;
            srow[k] = v;
            mx = fmaxf(mx, v);
        }
#pragma unroll
        for (int m = 1; m < 16; m <<= 1)
            mx = fmaxf(mx, __shfl_xor_sync(0xffffffffu, mx, m));

        float sum = 0.0f;
#pragma unroll 8
        for (int j = 0; j < Ssz / 16; j++) {
            const int k = il + (j << 4);
            float e = __expf(srow[k] - mx);
            sum += e;
            srow[k] = e;
        }
#pragma unroll
        for (int m = 1; m < 16; m <<= 1)
            sum += __shfl_xor_sync(0xffffffffu, sum, m);

        const float inv = 1.0f / sum;
#pragma unroll 8
        for (int j = 0; j < Ssz / 16; j++) {
            const int k = il + (j << 4);
            const float val = srow[k] * inv;
            arow[k] = val;
            reinterpret_cast<unsigned*>(srow)[k] = f2tf(val);
        }
    }
    __syncthreads();

    // ===== Phase 3: X = P @ V =====
    float xacc[4] = {0.0f, 0.0f, 0.0f, 0.0f};
    for (int kc = 0; kc < Ssz / CH; kc++) {
        // Stage V chunk [CH x 64] as tf32, layout [k][n] stride 72
#pragma unroll
        for (int i = 0; i < 16; i++) {
            const int idx = t + i * 256;
            const int r  = idx >> 4;
            const int c4 = (idx & 15) << 2;
            float4 v = *reinterpret_cast<const float4*>(
                Vg + (long)(kc * CH + r) * Dsz + c4);
            uint4 u = {f2tf(v.x), f2tf(v.y), f2tf(v.z), f2tf(v.w)};
            *reinterpret_cast<uint4*>(&KV[r * 72 + c4]) = u;
        }
        __syncthreads();

#pragma unroll 8
        for (int ks = 0; ks < CH / 8; ks++) {
            const int kg = kc * CH + ks * 8;   // global k for P
            const int kl = ks * 8;             // local k for V
            unsigned a0 = Ps[g * SC_STRIDE + kg + tg];
            unsigned a1 = Ps[(g + 8) * SC_STRIDE + kg + tg];
            unsigned a2 = Ps[g * SC_STRIDE + kg + tg + 4];
            unsigned a3 = Ps[(g + 8) * SC_STRIDE + kg + tg + 4];
            unsigned b0 = KV[(kl + tg) * 72 + warp * 8 + g];
            unsigned b1 = KV[(kl + tg + 4) * 72 + warp * 8 + g];
            mma_tf32(xacc, a0, a1, a2, a3, b0, b1);
        }
        __syncthreads();
    }

    // Write X tile: warp owns n-slice [warp*8, warp*8+8)
    {
        float* Xg = g_X + (long)b * Ssz * Dsz + h * DKsz;
        const int col = warp * 8 + tg * 2;
        float2 v0 = {xacc[0], xacc[1]};
        *reinterpret_cast<float2*>(Xg + (long)(row0 + g) * Dsz + col) = v0;
        float2 v1 = {xacc[2], xacc[3]};
        *reinterpret_cast<float2*>(Xg + (long)(row0 + g + 8) * Dsz + col) = v1;
    }
}

// ---------------------------------------------------------------------------
// Launch
// ---------------------------------------------------------------------------
extern "C" void kernel_launch(void* const* d_in, const int* in_sizes, int n_in,
                              void* d_out, int out_size) {
    const float* query = (const float*)d_in[0];
    const float* key   = (const float*)d_in[1];
    const float* value = (const float*)d_in[2];
    const int*   mask  = (const int*)d_in[3];
    const float* W_q   = (const float*)d_in[4];
    const float* W_k   = (const float*)d_in[5];
    const float* W_v   = (const float*)d_in[6];
    const float* W_o   = (const float*)d_in[7];

    float* out  = (float*)d_out;                        // (B,S,D)
    float* attn = out + (long)Bsz * Ssz * Dsz;          // (B,H,S,S)

    float *Q, *K, *V, *X;
    cudaGetSymbolAddress((void**)&Q, g_Q);
    cudaGetSymbolAddress((void**)&K, g_K);
    cudaGetSymbolAddress((void**)&V, g_V);
    cudaGetSymbolAddress((void**)&X, g_X);

    cudaFuncSetAttribute(attn_fused_kernel,
                         cudaFuncAttributeMaxDynamicSharedMemorySize, SM_TOTAL);

    dim3 projGrid(Dsz / 64, (Bsz * Ssz) / 128);         // (16, 32)
    proj_kernel<<<projGrid, 256>>>(query, W_q, Q);
    proj_kernel<<<projGrid, 256>>>(key,   W_k, K);
    proj_kernel<<<projGrid, 256>>>(value, W_v, V);

    attn_fused_kernel<<<dim3(Ssz / ROWS, BHsz), 256, SM_TOTAL>>>(mask, attn);

    proj_kernel<<<projGrid, 256>>>(X, W_o, out);
}

// round 8
// speedup vs baseline: 1.4024x; 1.4024x over previous
#include <cuda_runtime.h>
#include <math.h>

// Problem constants
#define Bsz 2
#define Ssz 2048
#define Dsz 1024
#define Hsz 16
#define DKsz 64
#define BHsz (Bsz * Hsz)

// Scratch (allocation-free rule: __device__ globals)
__device__ float g_Q[(long)Bsz * Ssz * Dsz];
__device__ float g_K[(long)Bsz * Ssz * Dsz];
__device__ float g_V[(long)Bsz * Ssz * Dsz];
__device__ float g_X[(long)Bsz * Ssz * Dsz];
// Per-row partial exp-sums: [z][row][colblock], colblock = 64-col scores block
__device__ float g_S[(long)BHsz * Ssz * 32];

__device__ __forceinline__ unsigned f2tf(float f) {
    unsigned u;
    asm("cvt.rna.tf32.f32 %0, %1;" : "=r"(u) : "f"(f));
    return u;
}

__device__ __forceinline__ void mma_tf32(float c[4], unsigned a0, unsigned a1,
                                         unsigned a2, unsigned a3,
                                         unsigned b0, unsigned b1) {
    asm volatile(
        "mma.sync.aligned.m16n8k8.row.col.f32.tf32.tf32.f32 "
        "{%0,%1,%2,%3}, {%4,%5,%6,%7}, {%8,%9}, {%0,%1,%2,%3};"
        : "+f"(c[0]), "+f"(c[1]), "+f"(c[2]), "+f"(c[3])
        : "r"(a0), "r"(a1), "r"(a2), "r"(a3), "r"(b0), "r"(b1));
}

// ---------------------------------------------------------------------------
// tf32 tensor-core GEMM for projections: C = A[M,K] @ B[K,N]
// Block tile 128x64, BK=32, 256 threads (8 warps, each 32x32 warp tile).
// ---------------------------------------------------------------------------
__device__ __forceinline__ void gemm_mma_nn(const float* __restrict__ A, int lda,
                                            const float* __restrict__ B, int ldb,
                                            float* __restrict__ C, int ldc,
                                            int K) {
    __shared__ __align__(16) unsigned As[128][36];
    __shared__ __align__(16) unsigned Bs[32][72];

    const int t    = threadIdx.x;
    const int lane = t & 31;
    const int warp = t >> 5;
    const int wm   = (warp & 3) * 32;
    const int wn   = (warp >> 2) * 32;
    const int g    = lane >> 2;
    const int tg   = lane & 3;

    const int row0 = blockIdx.y * 128;
    const int col0 = blockIdx.x * 64;

    float c[2][4][4];
#pragma unroll
    for (int mi = 0; mi < 2; mi++)
#pragma unroll
        for (int ni = 0; ni < 4; ni++)
#pragma unroll
            for (int r = 0; r < 4; r++) c[mi][ni][r] = 0.0f;

    for (int k0 = 0; k0 < K; k0 += 32) {
#pragma unroll
        for (int i = 0; i < 4; i++) {
            const int fidx = t + i * 256;
            const int r  = fidx >> 3;
            const int c4 = (fidx & 7) << 2;
            float4 v = *reinterpret_cast<const float4*>(
                A + (long)(row0 + r) * lda + k0 + c4);
            uint4 u = {f2tf(v.x), f2tf(v.y), f2tf(v.z), f2tf(v.w)};
            *reinterpret_cast<uint4*>(&As[r][c4]) = u;
        }
#pragma unroll
        for (int i = 0; i < 2; i++) {
            const int fidx = t + i * 256;
            const int r  = fidx >> 4;
            const int c4 = (fidx & 15) << 2;
            float4 v = *reinterpret_cast<const float4*>(
                B + (long)(k0 + r) * ldb + col0 + c4);
            uint4 u = {f2tf(v.x), f2tf(v.y), f2tf(v.z), f2tf(v.w)};
            *reinterpret_cast<uint4*>(&Bs[r][c4]) = u;
        }
        __syncthreads();

#pragma unroll
        for (int ks = 0; ks < 4; ks++) {
            const int k8 = ks * 8;
            unsigned a[2][4];
#pragma unroll
            for (int mi = 0; mi < 2; mi++) {
                const int mb = wm + mi * 16;
                a[mi][0] = As[mb + g][k8 + tg];
                a[mi][1] = As[mb + g + 8][k8 + tg];
                a[mi][2] = As[mb + g][k8 + tg + 4];
                a[mi][3] = As[mb + g + 8][k8 + tg + 4];
            }
#pragma unroll
            for (int ni = 0; ni < 4; ni++) {
                const int nb = wn + ni * 8;
                unsigned b0 = Bs[k8 + tg][nb + g];
                unsigned b1 = Bs[k8 + tg + 4][nb + g];
#pragma unroll
                for (int mi = 0; mi < 2; mi++)
                    mma_tf32(c[mi][ni], a[mi][0], a[mi][1], a[mi][2], a[mi][3],
                             b0, b1);
            }
        }
        __syncthreads();
    }

#pragma unroll
    for (int mi = 0; mi < 2; mi++) {
#pragma unroll
        for (int ni = 0; ni < 4; ni++) {
            const int row = row0 + wm + mi * 16 + g;
            const int col = col0 + wn + ni * 8 + tg * 2;
            float2 v0 = {c[mi][ni][0], c[mi][ni][1]};
            *reinterpret_cast<float2*>(C + (long)row * ldc + col) = v0;
            float2 v1 = {c[mi][ni][2], c[mi][ni][3]};
            *reinterpret_cast<float2*>(C + (long)(row + 8) * ldc + col) = v1;
        }
    }
}

__global__ void __launch_bounds__(256)
proj_kernel(const float* __restrict__ X,
            const float* __restrict__ W,
            float* __restrict__ Y) {
    gemm_mma_nn(X, Dsz, W, Dsz, Y, Dsz, Dsz);
}

// ---------------------------------------------------------------------------
// scores+exp kernel: E[z,q,k] = mask ? exp(Q.K/8 - 30) : 0, written to the
// attn buffer (unnormalized); per-row partial sums -> g_S[z][row][colblock].
// Block tile 128 rows x 64 cols, grid (32, 16, 32), 256 threads.
// ---------------------------------------------------------------------------
__global__ void __launch_bounds__(256)
scores_kernel(const int* __restrict__ mask, float* __restrict__ E) {
    __shared__ __align__(16) unsigned As[128][36];
    __shared__ __align__(16) unsigned Bs[64][36];
    __shared__ float red[128][9];

    const int t    = threadIdx.x;
    const int lane = t & 31;
    const int warp = t >> 5;
    const int wm   = (warp & 3) * 32;
    const int wn   = (warp >> 2) * 32;
    const int g    = lane >> 2;
    const int tg   = lane & 3;

    const int z = blockIdx.z;
    const int b = z >> 4, h = z & 15;
    const int row0 = blockIdx.y * 128;
    const int col0 = blockIdx.x * 64;

    const float* A  = g_Q + (long)b * Ssz * Dsz + h * DKsz;
    const float* Bm = g_K + (long)b * Ssz * Dsz + h * DKsz;
    float* Ez = E + (long)z * Ssz * Ssz;

    float c[2][4][4];
#pragma unroll
    for (int mi = 0; mi < 2; mi++)
#pragma unroll
        for (int ni = 0; ni < 4; ni++)
#pragma unroll
            for (int r = 0; r < 4; r++) c[mi][ni][r] = 0.0f;

#pragma unroll
    for (int k0 = 0; k0 < DKsz; k0 += 32) {
#pragma unroll
        for (int i = 0; i < 4; i++) {
            const int fidx = t + i * 256;
            const int r  = fidx >> 3;
            const int c4 = (fidx & 7) << 2;
            float4 v = *reinterpret_cast<const float4*>(
                A + (long)(row0 + r) * Dsz + k0 + c4);
            uint4 u = {f2tf(v.x), f2tf(v.y), f2tf(v.z), f2tf(v.w)};
            *reinterpret_cast<uint4*>(&As[r][c4]) = u;
        }
#pragma unroll
        for (int i = 0; i < 2; i++) {
            const int fidx = t + i * 256;
            const int r  = fidx >> 3;        // n in 0..63
            const int c4 = (fidx & 7) << 2;  // k
            float4 v = *reinterpret_cast<const float4*>(
                Bm + (long)(col0 + r) * Dsz + k0 + c4);
            uint4 u = {f2tf(v.x), f2tf(v.y), f2tf(v.z), f2tf(v.w)};
            *reinterpret_cast<uint4*>(&Bs[r][c4]) = u;
        }
        __syncthreads();

#pragma unroll
        for (int ks = 0; ks < 4; ks++) {
            const int k8 = ks * 8;
            unsigned a[2][4];
#pragma unroll
            for (int mi = 0; mi < 2; mi++) {
                const int mb = wm + mi * 16;
                a[mi][0] = As[mb + g][k8 + tg];
                a[mi][1] = As[mb + g + 8][k8 + tg];
                a[mi][2] = As[mb + g][k8 + tg + 4];
                a[mi][3] = As[mb + g + 8][k8 + tg + 4];
            }
#pragma unroll
            for (int ni = 0; ni < 4; ni++) {
                const int nb = wn + ni * 8;
                unsigned b0 = Bs[nb + g][k8 + tg];
                unsigned b1 = Bs[nb + g][k8 + tg + 4];
#pragma unroll
                for (int mi = 0; mi < 2; mi++)
                    mma_tf32(c[mi][ni], a[mi][0], a[mi][1], a[mi][2], a[mi][3],
                             b0, b1);
            }
        }
        __syncthreads();
    }

    // Epilogue: e = exp2((c/8 - 30) * log2e), masked; write E; row partials.
    const float SC  = 0.125f * 1.44269504088896f;
    const float CB  = -30.0f * 1.44269504088896f;
    float rsum[4] = {0.0f, 0.0f, 0.0f, 0.0f};

#pragma unroll
    for (int mi = 0; mi < 2; mi++) {
#pragma unroll
        for (int ni = 0; ni < 4; ni++) {
            const int r0  = wm + mi * 16 + g;
            const int col = col0 + wn + ni * 8 + tg * 2;
            const long mbase = (long)b * Ssz * Ssz + col;

            int2 m0 = *reinterpret_cast<const int2*>(
                mask + mbase + (long)(row0 + r0) * Ssz);
            float e00 = (m0.x == 0) ? 0.0f : exp2f(fmaf(c[mi][ni][0], SC, CB));
            float e01 = (m0.y == 0) ? 0.0f : exp2f(fmaf(c[mi][ni][1], SC, CB));

            int2 m1 = *reinterpret_cast<const int2*>(
                mask + mbase + (long)(row0 + r0 + 8) * Ssz);
            float e10 = (m1.x == 0) ? 0.0f : exp2f(fmaf(c[mi][ni][2], SC, CB));
            float e11 = (m1.y == 0) ? 0.0f : exp2f(fmaf(c[mi][ni][3], SC, CB));

            float2 v0 = {e00, e01};
            *reinterpret_cast<float2*>(Ez + (long)(row0 + r0) * Ssz + col) = v0;
            float2 v1 = {e10, e11};
            *reinterpret_cast<float2*>(Ez + (long)(row0 + r0 + 8) * Ssz + col) = v1;

            rsum[mi * 2]     += e00 + e01;
            rsum[mi * 2 + 1] += e10 + e11;
        }
    }

    const int sub = (warp >> 2) * 4 + tg;   // 0..7
#pragma unroll
    for (int mi = 0; mi < 2; mi++) {
        red[wm + mi * 16 + g][sub]     = rsum[mi * 2];
        red[wm + mi * 16 + g + 8][sub] = rsum[mi * 2 + 1];
    }
    __syncthreads();

    if (t < 128) {
        float s = 0.0f;
#pragma unroll
        for (int j = 0; j < 8; j++) s += red[t][j];
        g_S[((long)z * Ssz + row0 + t) * 32 + blockIdx.x] = s;
    }
}

// ---------------------------------------------------------------------------
// av+normalize kernel: reads E (in attn buffer), p = E * rinv, writes
// normalized attn in place (coalesced float4), X = P @ V.
// Block: 128 rows x 64 V-cols; grid (16, 32), 256 threads.
// ---------------------------------------------------------------------------
__global__ void __launch_bounds__(256)
av_kernel(float* __restrict__ attn) {
    __shared__ __align__(16) unsigned As[128][36];
    __shared__ __align__(16) unsigned Bs[32][72];
    __shared__ float rinv_s[128];

    const int t    = threadIdx.x;
    const int lane = t & 31;
    const int warp = t >> 5;
    const int wm   = (warp & 3) * 32;
    const int wn   = (warp >> 2) * 32;
    const int g    = lane >> 2;
    const int tg   = lane & 3;

    const int z = blockIdx.y;
    const int b = z >> 4, h = z & 15;
    const int row0 = blockIdx.x * 128;

    float* Ez = attn + (long)z * Ssz * Ssz;
    const float* Vg = g_V + (long)b * Ssz * Dsz + h * DKsz;

    // Row inverse sums
    if (t < 128) {
        const float* sp = g_S + ((long)z * Ssz + row0 + t) * 32;
        float s = 0.0f;
#pragma unroll
        for (int j = 0; j < 32; j++) s += sp[j];
        rinv_s[t] = 1.0f / s;
    }
    __syncthreads();

    float c[2][4][4];
#pragma unroll
    for (int mi = 0; mi < 2; mi++)
#pragma unroll
        for (int ni = 0; ni < 4; ni++)
#pragma unroll
            for (int r = 0; r < 4; r++) c[mi][ni][r] = 0.0f;

    for (int k0 = 0; k0 < Ssz; k0 += 32) {
        // Stage P chunk: read E, normalize, write attn in place, smem tf32
#pragma unroll
        for (int i = 0; i < 4; i++) {
            const int fidx = t + i * 256;
            const int r  = fidx >> 3;
            const int c4 = (fidx & 7) << 2;
            float* ep = Ez + (long)(row0 + r) * Ssz + k0 + c4;
            float4 ev = *reinterpret_cast<const float4*>(ep);
            const float ri = rinv_s[r];
            float4 pv = {ev.x * ri, ev.y * ri, ev.z * ri, ev.w * ri};
            *reinterpret_cast<float4*>(ep) = pv;
            uint4 u = {f2tf(pv.x), f2tf(pv.y), f2tf(pv.z), f2tf(pv.w)};
            *reinterpret_cast<uint4*>(&As[r][c4]) = u;
        }
        // Stage V chunk [32 k x 64 n]
#pragma unroll
        for (int i = 0; i < 2; i++) {
            const int fidx = t + i * 256;
            const int r  = fidx >> 4;
            const int c4 = (fidx & 15) << 2;
            float4 v = *reinterpret_cast<const float4*>(
                Vg + (long)(k0 + r) * Dsz + c4);
            uint4 u = {f2tf(v.x), f2tf(v.y), f2tf(v.z), f2tf(v.w)};
            *reinterpret_cast<uint4*>(&Bs[r][c4]) = u;
        }
        __syncthreads();

#pragma unroll
        for (int ks = 0; ks < 4; ks++) {
            const int k8 = ks * 8;
            unsigned a[2][4];
#pragma unroll
            for (int mi = 0; mi < 2; mi++) {
                const int mb = wm + mi * 16;
                a[mi][0] = As[mb + g][k8 + tg];
                a[mi][1] = As[mb + g + 8][k8 + tg];
                a[mi][2] = As[mb + g][k8 + tg + 4];
                a[mi][3] = As[mb + g + 8][k8 + tg + 4];
            }
#pragma unroll
            for (int ni = 0; ni < 4; ni++) {
                const int nb = wn + ni * 8;
                unsigned b0 = Bs[k8 + tg][nb + g];
                unsigned b1 = Bs[k8 + tg + 4][nb + g];
#pragma unroll
                for (int mi = 0; mi < 2; mi++)
                    mma_tf32(c[mi][ni], a[mi][0], a[mi][1], a[mi][2], a[mi][3],
                             b0, b1);
            }
        }
        __syncthreads();
    }

    // X epilogue
    float* Xg = g_X + (long)b * Ssz * Dsz + h * DKsz;
#pragma unroll
    for (int mi = 0; mi < 2; mi++) {
#pragma unroll
        for (int ni = 0; ni < 4; ni++) {
            const int row = row0 + wm + mi * 16 + g;
            const int col = wn + ni * 8 + tg * 2;
            float2 v0 = {c[mi][ni][0], c[mi][ni][1]};
            *reinterpret_cast<float2*>(Xg + (long)row * Dsz + col) = v0;
            float2 v1 = {c[mi][ni][2], c[mi][ni][3]};
            *reinterpret_cast<float2*>(Xg + (long)(row + 8) * Dsz + col) = v1;
        }
    }
}

// ---------------------------------------------------------------------------
// Launch
// ---------------------------------------------------------------------------
extern "C" void kernel_launch(void* const* d_in, const int* in_sizes, int n_in,
                              void* d_out, int out_size) {
    const float* query = (const float*)d_in[0];
    const float* key   = (const float*)d_in[1];
    const float* value = (const float*)d_in[2];
    const int*   mask  = (const int*)d_in[3];
    const float* W_q   = (const float*)d_in[4];
    const float* W_k   = (const float*)d_in[5];
    const float* W_v   = (const float*)d_in[6];
    const float* W_o   = (const float*)d_in[7];

    float* out  = (float*)d_out;                        // (B,S,D)
    float* attn = out + (long)Bsz * Ssz * Dsz;          // (B,H,S,S)

    float *Q, *K, *V, *X;
    cudaGetSymbolAddress((void**)&Q, g_Q);
    cudaGetSymbolAddress((void**)&K, g_K);
    cudaGetSymbolAddress((void**)&V, g_V);
    cudaGetSymbolAddress((void**)&X, g_X);

    dim3 projGrid(Dsz / 64, (Bsz * Ssz) / 128);         // (16, 32)
    proj_kernel<<<projGrid, 256>>>(query, W_q, Q);
    proj_kernel<<<projGrid, 256>>>(key,   W_k, K);
    proj_kernel<<<projGrid, 256>>>(value, W_v, V);

    scores_kernel<<<dim3(Ssz / 64, Ssz / 128, BHsz), 256>>>(mask, attn);
    av_kernel<<<dim3(Ssz / 128, BHsz), 256>>>(attn);

    proj_kernel<<<projGrid, 256>>>(X, W_o, out);
}

// round 10
// speedup vs baseline: 1.8232x; 1.3001x over previous
#include <cuda_runtime.h>
#include <math.h>

// Problem constants
#define Bsz 2
#define Ssz 2048
#define Dsz 1024
#define Hsz 16
#define DKsz 64
#define BHsz (Bsz * Hsz)

// Scratch (allocation-free rule: __device__ globals)
__device__ float g_Q[(long)Bsz * Ssz * Dsz];
__device__ float g_K[(long)Bsz * Ssz * Dsz];
__device__ float g_V[(long)Bsz * Ssz * Dsz];
__device__ float g_X[(long)Bsz * Ssz * Dsz];
// Per-row partial exp-sums: [z][row][colblock], colblock = 64-col scores block
__device__ float g_S[(long)BHsz * Ssz * 32];

__device__ __forceinline__ unsigned f2tf(float f) {
    unsigned u;
    asm("cvt.rna.tf32.f32 %0, %1;" : "=r"(u) : "f"(f));
    return u;
}

__device__ __forceinline__ void mma_tf32(float c[4], unsigned a0, unsigned a1,
                                         unsigned a2, unsigned a3,
                                         unsigned b0, unsigned b1) {
    asm volatile(
        "mma.sync.aligned.m16n8k8.row.col.f32.tf32.tf32.f32 "
        "{%0,%1,%2,%3}, {%4,%5,%6,%7}, {%8,%9}, {%0,%1,%2,%3};"
        : "+f"(c[0]), "+f"(c[1]), "+f"(c[2]), "+f"(c[3])
        : "r"(a0), "r"(a1), "r"(a2), "r"(a3), "r"(b0), "r"(b1));
}

// ---------------------------------------------------------------------------
// tf32 tensor-core GEMM for projections: C = A[M,K] @ B[K,N]
// Block tile 128x64, BK=32, 256 threads (8 warps, each 32x32 warp tile).
// ---------------------------------------------------------------------------
__device__ __forceinline__ void gemm_mma_nn(const float* __restrict__ A, int lda,
                                            const float* __restrict__ B, int ldb,
                                            float* __restrict__ C, int ldc,
                                            int K) {
    __shared__ __align__(16) unsigned As[128][36];
    __shared__ __align__(16) unsigned Bs[32][72];

    const int t    = threadIdx.x;
    const int lane = t & 31;
    const int warp = t >> 5;
    const int wm   = (warp & 3) * 32;
    const int wn   = (warp >> 2) * 32;
    const int g    = lane >> 2;
    const int tg   = lane & 3;

    const int row0 = blockIdx.y * 128;
    const int col0 = blockIdx.x * 64;

    float c[2][4][4];
#pragma unroll
    for (int mi = 0; mi < 2; mi++)
#pragma unroll
        for (int ni = 0; ni < 4; ni++)
#pragma unroll
            for (int r = 0; r < 4; r++) c[mi][ni][r] = 0.0f;

    for (int k0 = 0; k0 < K; k0 += 32) {
#pragma unroll
        for (int i = 0; i < 4; i++) {
            const int fidx = t + i * 256;
            const int r  = fidx >> 3;
            const int c4 = (fidx & 7) << 2;
            float4 v = *reinterpret_cast<const float4*>(
                A + (long)(row0 + r) * lda + k0 + c4);
            uint4 u = {f2tf(v.x), f2tf(v.y), f2tf(v.z), f2tf(v.w)};
            *reinterpret_cast<uint4*>(&As[r][c4]) = u;
        }
#pragma unroll
        for (int i = 0; i < 2; i++) {
            const int fidx = t + i * 256;
            const int r  = fidx >> 4;
            const int c4 = (fidx & 15) << 2;
            float4 v = *reinterpret_cast<const float4*>(
                B + (long)(k0 + r) * ldb + col0 + c4);
            uint4 u = {f2tf(v.x), f2tf(v.y), f2tf(v.z), f2tf(v.w)};
            *reinterpret_cast<uint4*>(&Bs[r][c4]) = u;
        }
        __syncthreads();

#pragma unroll
        for (int ks = 0; ks < 4; ks++) {
            const int k8 = ks * 8;
            unsigned a[2][4];
#pragma unroll
            for (int mi = 0; mi < 2; mi++) {
                const int mb = wm + mi * 16;
                a[mi][0] = As[mb + g][k8 + tg];
                a[mi][1] = As[mb + g + 8][k8 + tg];
                a[mi][2] = As[mb + g][k8 + tg + 4];
                a[mi][3] = As[mb + g + 8][k8 + tg + 4];
            }
#pragma unroll
            for (int ni = 0; ni < 4; ni++) {
                const int nb = wn + ni * 8;
                unsigned b0 = Bs[k8 + tg][nb + g];
                unsigned b1 = Bs[k8 + tg + 4][nb + g];
#pragma unroll
                for (int mi = 0; mi < 2; mi++)
                    mma_tf32(c[mi][ni], a[mi][0], a[mi][1], a[mi][2], a[mi][3],
                             b0, b1);
            }
        }
        __syncthreads();
    }

#pragma unroll
    for (int mi = 0; mi < 2; mi++) {
#pragma unroll
        for (int ni = 0; ni < 4; ni++) {
            const int row = row0 + wm + mi * 16 + g;
            const int col = col0 + wn + ni * 8 + tg * 2;
            float2 v0 = {c[mi][ni][0], c[mi][ni][1]};
            *reinterpret_cast<float2*>(C + (long)row * ldc + col) = v0;
            float2 v1 = {c[mi][ni][2], c[mi][ni][3]};
            *reinterpret_cast<float2*>(C + (long)(row + 8) * ldc + col) = v1;
        }
    }
}

__global__ void __launch_bounds__(256, 4)
proj_kernel(const float* __restrict__ X,
            const float* __restrict__ W,
            float* __restrict__ Y) {
    gemm_mma_nn(X, Dsz, W, Dsz, Y, Dsz, Dsz);
}

// ---------------------------------------------------------------------------
// scores+exp kernel: E[z,q,k] = mask ? exp(Q.K/8 - 30) : 0, written to the
// attn buffer (unnormalized); per-row partial sums -> g_S[z][row][colblock].
// Block tile 128 rows x 64 cols, grid (32, 16, 32), 256 threads.
// ---------------------------------------------------------------------------
__global__ void __launch_bounds__(256, 4)
scores_kernel(const int* __restrict__ mask, float* __restrict__ E) {
    __shared__ __align__(16) unsigned As[128][36];
    __shared__ __align__(16) unsigned Bs[64][36];
    __shared__ float red[128][9];

    const int t    = threadIdx.x;
    const int lane = t & 31;
    const int warp = t >> 5;
    const int wm   = (warp & 3) * 32;
    const int wn   = (warp >> 2) * 32;
    const int g    = lane >> 2;
    const int tg   = lane & 3;

    const int z = blockIdx.z;
    const int b = z >> 4, h = z & 15;
    const int row0 = blockIdx.y * 128;
    const int col0 = blockIdx.x * 64;

    const float* A  = g_Q + (long)b * Ssz * Dsz + h * DKsz;
    const float* Bm = g_K + (long)b * Ssz * Dsz + h * DKsz;
    float* Ez = E + (long)z * Ssz * Ssz;

    float c[2][4][4];
#pragma unroll
    for (int mi = 0; mi < 2; mi++)
#pragma unroll
        for (int ni = 0; ni < 4; ni++)
#pragma unroll
            for (int r = 0; r < 4; r++) c[mi][ni][r] = 0.0f;

#pragma unroll
    for (int k0 = 0; k0 < DKsz; k0 += 32) {
#pragma unroll
        for (int i = 0; i < 4; i++) {
            const int fidx = t + i * 256;
            const int r  = fidx >> 3;
            const int c4 = (fidx & 7) << 2;
            float4 v = *reinterpret_cast<const float4*>(
                A + (long)(row0 + r) * Dsz + k0 + c4);
            uint4 u = {f2tf(v.x), f2tf(v.y), f2tf(v.z), f2tf(v.w)};
            *reinterpret_cast<uint4*>(&As[r][c4]) = u;
        }
#pragma unroll
        for (int i = 0; i < 2; i++) {
            const int fidx = t + i * 256;
            const int r  = fidx >> 3;        // n in 0..63
            const int c4 = (fidx & 7) << 2;  // k
            float4 v = *reinterpret_cast<const float4*>(
                Bm + (long)(col0 + r) * Dsz + k0 + c4);
            uint4 u = {f2tf(v.x), f2tf(v.y), f2tf(v.z), f2tf(v.w)};
            *reinterpret_cast<uint4*>(&Bs[r][c4]) = u;
        }
        __syncthreads();

#pragma unroll
        for (int ks = 0; ks < 4; ks++) {
            const int k8 = ks * 8;
            unsigned a[2][4];
#pragma unroll
            for (int mi = 0; mi < 2; mi++) {
                const int mb = wm + mi * 16;
                a[mi][0] = As[mb + g][k8 + tg];
                a[mi][1] = As[mb + g + 8][k8 + tg];
                a[mi][2] = As[mb + g][k8 + tg + 4];
                a[mi][3] = As[mb + g + 8][k8 + tg + 4];
            }
#pragma unroll
            for (int ni = 0; ni < 4; ni++) {
                const int nb = wn + ni * 8;
                unsigned b0 = Bs[nb + g][k8 + tg];
                unsigned b1 = Bs[nb + g][k8 + tg + 4];
#pragma unroll
                for (int mi = 0; mi < 2; mi++)
                    mma_tf32(c[mi][ni], a[mi][0], a[mi][1], a[mi][2], a[mi][3],
                             b0, b1);
            }
        }
        __syncthreads();
    }

    // Epilogue: e = exp2((c/8 - 30) * log2e), masked; write E; row partials.
    const float SC  = 0.125f * 1.44269504088896f;
    const float CB  = -30.0f * 1.44269504088896f;
    float rsum[4] = {0.0f, 0.0f, 0.0f, 0.0f};

#pragma unroll
    for (int mi = 0; mi < 2; mi++) {
#pragma unroll
        for (int ni = 0; ni < 4; ni++) {
            const int r0  = wm + mi * 16 + g;
            const int col = col0 + wn + ni * 8 + tg * 2;
            const long mbase = (long)b * Ssz * Ssz + col;

            int2 m0 = *reinterpret_cast<const int2*>(
                mask + mbase + (long)(row0 + r0) * Ssz);
            float e00 = (m0.x == 0) ? 0.0f : exp2f(fmaf(c[mi][ni][0], SC, CB));
            float e01 = (m0.y == 0) ? 0.0f : exp2f(fmaf(c[mi][ni][1], SC, CB));

            int2 m1 = *reinterpret_cast<const int2*>(
                mask + mbase + (long)(row0 + r0 + 8) * Ssz);
            float e10 = (m1.x == 0) ? 0.0f : exp2f(fmaf(c[mi][ni][2], SC, CB));
            float e11 = (m1.y == 0) ? 0.0f : exp2f(fmaf(c[mi][ni][3], SC, CB));

            float2 v0 = {e00, e01};
            *reinterpret_cast<float2*>(Ez + (long)(row0 + r0) * Ssz + col) = v0;
            float2 v1 = {e10, e11};
            *reinterpret_cast<float2*>(Ez + (long)(row0 + r0 + 8) * Ssz + col) = v1;

            rsum[mi * 2]     += e00 + e01;
            rsum[mi * 2 + 1] += e10 + e11;
        }
    }

    const int sub = (warp >> 2) * 4 + tg;   // 0..7
#pragma unroll
    for (int mi = 0; mi < 2; mi++) {
        red[wm + mi * 16 + g][sub]     = rsum[mi * 2];
        red[wm + mi * 16 + g + 8][sub] = rsum[mi * 2 + 1];
    }
    __syncthreads();

    if (t < 128) {
        float s = 0.0f;
#pragma unroll
        for (int j = 0; j < 8; j++) s += red[t][j];
        g_S[((long)z * Ssz + row0 + t) * 32 + blockIdx.x] = s;
    }
}

// ---------------------------------------------------------------------------
// av kernel: pure X = E @ V GEMM with row-scale epilogue (X *= rinv).
// Normalization commutes: X = diag(1/rsum) * (E @ V).
// Block: 128 rows x 64 V-cols; grid (16, 32), 256 threads.
// ---------------------------------------------------------------------------
__global__ void __launch_bounds__(256, 4)
av_kernel(const float* __restrict__ E) {
    __shared__ __align__(16) unsigned As[128][36];
    __shared__ __align__(16) unsigned Bs[32][72];
    __shared__ float rinv_s[128];

    const int t    = threadIdx.x;
    const int lane = t & 31;
    const int warp = t >> 5;
    const int wm   = (warp & 3) * 32;
    const int wn   = (warp >> 2) * 32;
    const int g    = lane >> 2;
    const int tg   = lane & 3;

    const int z = blockIdx.y;
    const int b = z >> 4, h = z & 15;
    const int row0 = blockIdx.x * 128;

    const float* Ez = E + (long)z * Ssz * Ssz;
    const float* Vg = g_V + (long)b * Ssz * Dsz + h * DKsz;

    // Row inverse sums
    if (t < 128) {
        const float* sp = g_S + ((long)z * Ssz + row0 + t) * 32;
        float s = 0.0f;
#pragma unroll
        for (int j = 0; j < 32; j++) s += sp[j];
        rinv_s[t] = 1.0f / s;
    }
    __syncthreads();

    float c[2][4][4];
#pragma unroll
    for (int mi = 0; mi < 2; mi++)
#pragma unroll
        for (int ni = 0; ni < 4; ni++)
#pragma unroll
            for (int r = 0; r < 4; r++) c[mi][ni][r] = 0.0f;

    for (int k0 = 0; k0 < Ssz; k0 += 32) {
        // Stage E chunk as tf32 (no normalization here)
#pragma unroll
        for (int i = 0; i < 4; i++) {
            const int fidx = t + i * 256;
            const int r  = fidx >> 3;
            const int c4 = (fidx & 7) << 2;
            float4 ev = *reinterpret_cast<const float4*>(
                Ez + (long)(row0 + r) * Ssz + k0 + c4);
            uint4 u = {f2tf(ev.x), f2tf(ev.y), f2tf(ev.z), f2tf(ev.w)};
            *reinterpret_cast<uint4*>(&As[r][c4]) = u;
        }
        // Stage V chunk [32 k x 64 n]
#pragma unroll
        for (int i = 0; i < 2; i++) {
            const int fidx = t + i * 256;
            const int r  = fidx >> 4;
            const int c4 = (fidx & 15) << 2;
            float4 v = *reinterpret_cast<const float4*>(
                Vg + (long)(k0 + r) * Dsz + c4);
            uint4 u = {f2tf(v.x), f2tf(v.y), f2tf(v.z), f2tf(v.w)};
            *reinterpret_cast<uint4*>(&Bs[r][c4]) = u;
        }
        __syncthreads();

#pragma unroll
        for (int ks = 0; ks < 4; ks++) {
            const int k8 = ks * 8;
            unsigned a[2][4];
#pragma unroll
            for (int mi = 0; mi < 2; mi++) {
                const int mb = wm + mi * 16;
                a[mi][0] = As[mb + g][k8 + tg];
                a[mi][1] = As[mb + g + 8][k8 + tg];
                a[mi][2] = As[mb + g][k8 + tg + 4];
                a[mi][3] = As[mb + g + 8][k8 + tg + 4];
            }
#pragma unroll
            for (int ni = 0; ni < 4; ni++) {
                const int nb = wn + ni * 8;
                unsigned b0 = Bs[k8 + tg][nb + g];
                unsigned b1 = Bs[k8 + tg + 4][nb + g];
#pragma unroll
                for (int mi = 0; mi < 2; mi++)
                    mma_tf32(c[mi][ni], a[mi][0], a[mi][1], a[mi][2], a[mi][3],
                             b0, b1);
            }
        }
        __syncthreads();
    }

    // X epilogue with row scaling
    float* Xg = g_X + (long)b * Ssz * Dsz + h * DKsz;
#pragma unroll
    for (int mi = 0; mi < 2; mi++) {
#pragma unroll
        for (int ni = 0; ni < 4; ni++) {
            const int r0  = wm + mi * 16 + g;
            const int col = wn + ni * 8 + tg * 2;
            const float ri0 = rinv_s[r0];
            const float ri1 = rinv_s[r0 + 8];
            float2 v0 = {c[mi][ni][0] * ri0, c[mi][ni][1] * ri0};
            *reinterpret_cast<float2*>(Xg + (long)(row0 + r0) * Dsz + col) = v0;
            float2 v1 = {c[mi][ni][2] * ri1, c[mi][ni][3] * ri1};
            *reinterpret_cast<float2*>(Xg + (long)(row0 + r0 + 8) * Dsz + col) = v1;
        }
    }
}

// ---------------------------------------------------------------------------
// norm kernel: attn = E * rinv, in place, streaming. One block per row.
// grid (Ssz, BHsz), 256 threads; 8 elements (2 float4) per thread.
// ---------------------------------------------------------------------------
__global__ void __launch_bounds__(256)
norm_kernel(float* __restrict__ attn) {
    const int row = blockIdx.x;
    const int z   = blockIdx.y;
    const int t   = threadIdx.x;

    __shared__ float rinv_sh;
    if (t < 32) {
        float s = g_S[((long)z * Ssz + row) * 32 + t];
#pragma unroll
        for (int m = 16; m > 0; m >>= 1)
            s += __shfl_xor_sync(0xffffffffu, s, m);
        if (t == 0) rinv_sh = 1.0f / s;
    }
    __syncthreads();
    const float ri = rinv_sh;

    float* rp = attn + ((long)z * Ssz + row) * Ssz;
#pragma unroll
    for (int i = 0; i < 2; i++) {
        const int idx = (t + i * 256) * 4;
        float4 v = *reinterpret_cast<const float4*>(rp + idx);
        v.x *= ri; v.y *= ri; v.z *= ri; v.w *= ri;
        *reinterpret_cast<float4*>(rp + idx) = v;
    }
}

// ---------------------------------------------------------------------------
// Launch
// ---------------------------------------------------------------------------
extern "C" void kernel_launch(void* const* d_in, const int* in_sizes, int n_in,
                              void* d_out, int out_size) {
    const float* query = (const float*)d_in[0];
    const float* key   = (const float*)d_in[1];
    const float* value = (const float*)d_in[2];
    const int*   mask  = (const int*)d_in[3];
    const float* W_q   = (const float*)d_in[4];
    const float* W_k   = (const float*)d_in[5];
    const float* W_v   = (const float*)d_in[6];
    const float* W_o   = (const float*)d_in[7];

    float* out  = (float*)d_out;                        // (B,S,D)
    float* attn = out + (long)Bsz * Ssz * Dsz;          // (B,H,S,S)

    float *Q, *K, *V, *X;
    cudaGetSymbolAddress((void**)&Q, g_Q);
    cudaGetSymbolAddress((void**)&K, g_K);
    cudaGetSymbolAddress((void**)&V, g_V);
    cudaGetSymbolAddress((void**)&X, g_X);

    dim3 projGrid(Dsz / 64, (Bsz * Ssz) / 128);         // (16, 32)
    proj_kernel<<<projGrid, 256>>>(query, W_q, Q);
    proj_kernel<<<projGrid, 256>>>(key,   W_k, K);
    proj_kernel<<<projGrid, 256>>>(value, W_v, V);

    scores_kernel<<<dim3(Ssz / 64, Ssz / 128, BHsz), 256>>>(mask, attn);
    av_kernel<<<dim3(Ssz / 128, BHsz), 256>>>(attn);    // reads E before norm
    norm_kernel<<<dim3(Ssz, BHsz), 256>>>(attn);        // E -> P in place

    proj_kernel<<<projGrid, 256>>>(X, W_o, out);
}

// round 11
// speedup vs baseline: 1.8561x; 1.0180x over previous
#include <cuda_runtime.h>
#include <math.h>

// Problem constants
#define Bsz 2
#define Ssz 2048
#define Dsz 1024
#define Hsz 16
#define DKsz 64
#define BHsz (Bsz * Hsz)

// Scratch (allocation-free rule: __device__ globals)
__device__ float g_Q[(long)Bsz * Ssz * Dsz];
__device__ float g_K[(long)Bsz * Ssz * Dsz];
__device__ float g_V[(long)Bsz * Ssz * Dsz];
__device__ float g_X[(long)Bsz * Ssz * Dsz];
// Per-row exp-sums (full row sum, computed by fused kernel)
__device__ float g_S[(long)BHsz * Ssz];

__device__ __forceinline__ unsigned f2tf(float f) {
    unsigned u;
    asm("cvt.rna.tf32.f32 %0, %1;" : "=r"(u) : "f"(f));
    return u;
}

__device__ __forceinline__ void mma_tf32(float c[4], unsigned a0, unsigned a1,
                                         unsigned a2, unsigned a3,
                                         unsigned b0, unsigned b1) {
    asm volatile(
        "mma.sync.aligned.m16n8k8.row.col.f32.tf32.tf32.f32 "
        "{%0,%1,%2,%3}, {%4,%5,%6,%7}, {%8,%9}, {%0,%1,%2,%3};"
        : "+f"(c[0]), "+f"(c[1]), "+f"(c[2]), "+f"(c[3])
        : "r"(a0), "r"(a1), "r"(a2), "r"(a3), "r"(b0), "r"(b1));
}

// ---------------------------------------------------------------------------
// tf32 tensor-core GEMM for projections: C = A[M,K] @ B[K,N]
// Block tile 128x64, BK=32, 256 threads (8 warps, each 32x32 warp tile).
// ---------------------------------------------------------------------------
__device__ __forceinline__ void gemm_mma_nn(const float* __restrict__ A, int lda,
                                            const float* __restrict__ B, int ldb,
                                            float* __restrict__ C, int ldc,
                                            int K) {
    __shared__ __align__(16) unsigned As[128][36];
    __shared__ __align__(16) unsigned Bs[32][72];

    const int t    = threadIdx.x;
    const int lane = t & 31;
    const int warp = t >> 5;
    const int wm   = (warp & 3) * 32;
    const int wn   = (warp >> 2) * 32;
    const int g    = lane >> 2;
    const int tg   = lane & 3;

    const int row0 = blockIdx.y * 128;
    const int col0 = blockIdx.x * 64;

    float c[2][4][4];
#pragma unroll
    for (int mi = 0; mi < 2; mi++)
#pragma unroll
        for (int ni = 0; ni < 4; ni++)
#pragma unroll
            for (int r = 0; r < 4; r++) c[mi][ni][r] = 0.0f;

    for (int k0 = 0; k0 < K; k0 += 32) {
#pragma unroll
        for (int i = 0; i < 4; i++) {
            const int fidx = t + i * 256;
            const int r  = fidx >> 3;
            const int c4 = (fidx & 7) << 2;
            float4 v = *reinterpret_cast<const float4*>(
                A + (long)(row0 + r) * lda + k0 + c4);
            uint4 u = {f2tf(v.x), f2tf(v.y), f2tf(v.z), f2tf(v.w)};
            *reinterpret_cast<uint4*>(&As[r][c4]) = u;
        }
#pragma unroll
        for (int i = 0; i < 2; i++) {
            const int fidx = t + i * 256;
            const int r  = fidx >> 4;
            const int c4 = (fidx & 15) << 2;
            float4 v = *reinterpret_cast<const float4*>(
                B + (long)(k0 + r) * ldb + col0 + c4);
            uint4 u = {f2tf(v.x), f2tf(v.y), f2tf(v.z), f2tf(v.w)};
            *reinterpret_cast<uint4*>(&Bs[r][c4]) = u;
        }
        __syncthreads();

#pragma unroll
        for (int ks = 0; ks < 4; ks++) {
            const int k8 = ks * 8;
            unsigned a[2][4];
#pragma unroll
            for (int mi = 0; mi < 2; mi++) {
                const int mb = wm + mi * 16;
                a[mi][0] = As[mb + g][k8 + tg];
                a[mi][1] = As[mb + g + 8][k8 + tg];
                a[mi][2] = As[mb + g][k8 + tg + 4];
                a[mi][3] = As[mb + g + 8][k8 + tg + 4];
            }
#pragma unroll
            for (int ni = 0; ni < 4; ni++) {
                const int nb = wn + ni * 8;
                unsigned b0 = Bs[k8 + tg][nb + g];
                unsigned b1 = Bs[k8 + tg + 4][nb + g];
#pragma unroll
                for (int mi = 0; mi < 2; mi++)
                    mma_tf32(c[mi][ni], a[mi][0], a[mi][1], a[mi][2], a[mi][3],
                             b0, b1);
            }
        }
        __syncthreads();
    }

#pragma unroll
    for (int mi = 0; mi < 2; mi++) {
#pragma unroll
        for (int ni = 0; ni < 4; ni++) {
            const int row = row0 + wm + mi * 16 + g;
            const int col = col0 + wn + ni * 8 + tg * 2;
            float2 v0 = {c[mi][ni][0], c[mi][ni][1]};
            *reinterpret_cast<float2*>(C + (long)row * ldc + col) = v0;
            float2 v1 = {c[mi][ni][2], c[mi][ni][3]};
            *reinterpret_cast<float2*>(C + (long)(row + 8) * ldc + col) = v1;
        }
    }
}

__global__ void __launch_bounds__(256, 4)
proj_kernel(const float* __restrict__ X,
            const float* __restrict__ W,
            float* __restrict__ Y) {
    gemm_mma_nn(X, Dsz, W, Dsz, Y, Dsz, Dsz);
}

// ---------------------------------------------------------------------------
// Fused scores + exp + AV kernel.
// Block: 128 q-rows x one z, streams K/V in 64-col chunks.
// Per chunk: S = QK^T (MMA) -> e = mask ? exp(S/8-30) : 0 -> write E to gmem,
// tf32 copy in smem -> X += E_chunk @ V_chunk (MMA). rsum in regs.
// Epilogue: reduce rsum per row -> g_S, X *= 1/rsum -> g_X.
// Dynamic smem:
//   Qs [128][68] u32  34816 B
//   Ks [ 64][68] u32  17408 B
//   Vs [ 64][72] u32  18432 B
//   Es [128][68] u32  34816 B
//   red[128][9]  f32   4608 B
//   rinv[128]    f32    512 B     total 110592 B -> 2 CTAs/SM
// grid (Ssz/128 = 16, BHsz = 32), 256 threads.
// ---------------------------------------------------------------------------
#define FA_SMEM 110592

__global__ void __launch_bounds__(256, 2)
fused_attn_kernel(const int* __restrict__ mask, float* __restrict__ E) {
    extern __shared__ __align__(16) unsigned sm[];
    unsigned* Qs   = sm;                              // [128][68]
    unsigned* Ks   = Qs + 128 * 68;                   // [64][68]
    unsigned* Vs   = Ks + 64 * 68;                    // [64][72]
    unsigned* Es   = Vs + 64 * 72;                    // [128][68]
    float*    red  = reinterpret_cast<float*>(Es + 128 * 68);  // [128][9]
    float*    rinv = red + 128 * 9;                   // [128]

    const int t    = threadIdx.x;
    const int lane = t & 31;
    const int warp = t >> 5;
    const int wm   = (warp & 3) * 32;
    const int wn   = (warp >> 2) * 32;
    const int g    = lane >> 2;
    const int tg   = lane & 3;

    const int z = blockIdx.y;
    const int b = z >> 4, h = z & 15;
    const int row0 = blockIdx.x * 128;

    const float* Qg = g_Q + (long)b * Ssz * Dsz + h * DKsz;
    const float* Kg = g_K + (long)b * Ssz * Dsz + h * DKsz;
    const float* Vg = g_V + (long)b * Ssz * Dsz + h * DKsz;
    float* Ez = E + (long)z * Ssz * Ssz;

    // Stage Q tile [128 x 64] as tf32 (once)
#pragma unroll
    for (int i = 0; i < 8; i++) {
        const int fidx = t + i * 256;
        const int r  = fidx >> 4;
        const int c4 = (fidx & 15) << 2;
        float4 v = *reinterpret_cast<const float4*>(
            Qg + (long)(row0 + r) * Dsz + c4);
        uint4 u = {f2tf(v.x), f2tf(v.y), f2tf(v.z), f2tf(v.w)};
        *reinterpret_cast<uint4*>(&Qs[r * 68 + c4]) = u;
    }

    float xacc[2][4][4];
#pragma unroll
    for (int mi = 0; mi < 2; mi++)
#pragma unroll
        for (int ni = 0; ni < 4; ni++)
#pragma unroll
            for (int r = 0; r < 4; r++) xacc[mi][ni][r] = 0.0f;
    float rsum[4] = {0.0f, 0.0f, 0.0f, 0.0f};

    const float SC = 0.125f * 1.44269504088896f;
    const float CB = -30.0f * 1.44269504088896f;

    for (int c = 0; c < Ssz / 64; c++) {
        __syncthreads();   // prior chunk's MMAs done before Ks/Vs/Es overwrite

        // Stage K chunk [64 n x 64 k], NT layout stride 68
#pragma unroll
        for (int i = 0; i < 4; i++) {
            const int fidx = t + i * 256;
            const int r  = fidx >> 4;
            const int c4 = (fidx & 15) << 2;
            float4 v = *reinterpret_cast<const float4*>(
                Kg + (long)(c * 64 + r) * Dsz + c4);
            uint4 u = {f2tf(v.x), f2tf(v.y), f2tf(v.z), f2tf(v.w)};
            *reinterpret_cast<uint4*>(&Ks[r * 68 + c4]) = u;
        }
        __syncthreads();

        // QK^T MMA: S chunk [128 x 64], K depth 64
        float sacc[2][4][4];
#pragma unroll
        for (int mi = 0; mi < 2; mi++)
#pragma unroll
            for (int ni = 0; ni < 4; ni++)
#pragma unroll
                for (int r = 0; r < 4; r++) sacc[mi][ni][r] = 0.0f;

#pragma unroll
        for (int ks = 0; ks < 8; ks++) {
            const int k8 = ks * 8;
            unsigned a[2][4];
#pragma unroll
            for (int mi = 0; mi < 2; mi++) {
                const int mb = wm + mi * 16;
                a[mi][0] = Qs[(mb + g) * 68 + k8 + tg];
                a[mi][1] = Qs[(mb + g + 8) * 68 + k8 + tg];
                a[mi][2] = Qs[(mb + g) * 68 + k8 + tg + 4];
                a[mi][3] = Qs[(mb + g + 8) * 68 + k8 + tg + 4];
            }
#pragma unroll
            for (int ni = 0; ni < 4; ni++) {
                const int nb = wn + ni * 8;
                unsigned b0 = Ks[(nb + g) * 68 + k8 + tg];
                unsigned b1 = Ks[(nb + g) * 68 + k8 + tg + 4];
#pragma unroll
                for (int mi = 0; mi < 2; mi++)
                    mma_tf32(sacc[mi][ni], a[mi][0], a[mi][1], a[mi][2],
                             a[mi][3], b0, b1);
            }
        }

        // Epilogue: masked exp; write E to gmem (fp32) + Es smem (tf32); rsum
#pragma unroll
        for (int mi = 0; mi < 2; mi++) {
#pragma unroll
            for (int ni = 0; ni < 4; ni++) {
                const int r0   = wm + mi * 16 + g;
                const int col  = wn + ni * 8 + tg * 2;
                const int gcol = c * 64 + col;
                const long mbase = (long)b * Ssz * Ssz + gcol;

                int2 m0 = *reinterpret_cast<const int2*>(
                    mask + mbase + (long)(row0 + r0) * Ssz);
                float e00 = (m0.x == 0) ? 0.0f : exp2f(fmaf(sacc[mi][ni][0], SC, CB));
                float e01 = (m0.y == 0) ? 0.0f : exp2f(fmaf(sacc[mi][ni][1], SC, CB));

                int2 m1 = *reinterpret_cast<const int2*>(
                    mask + mbase + (long)(row0 + r0 + 8) * Ssz);
                float e10 = (m1.x == 0) ? 0.0f : exp2f(fmaf(sacc[mi][ni][2], SC, CB));
                float e11 = (m1.y == 0) ? 0.0f : exp2f(fmaf(sacc[mi][ni][3], SC, CB));

                float2 v0 = {e00, e01};
                *reinterpret_cast<float2*>(
                    Ez + (long)(row0 + r0) * Ssz + gcol) = v0;
                float2 v1 = {e10, e11};
                *reinterpret_cast<float2*>(
                    Ez + (long)(row0 + r0 + 8) * Ssz + gcol) = v1;

                Es[r0 * 68 + col]           = f2tf(e00);
                Es[r0 * 68 + col + 1]       = f2tf(e01);
                Es[(r0 + 8) * 68 + col]     = f2tf(e10);
                Es[(r0 + 8) * 68 + col + 1] = f2tf(e11);

                rsum[mi * 2]     += e00 + e01;
                rsum[mi * 2 + 1] += e10 + e11;
            }
        }

        // Stage V chunk [64 k x 64 n], NN layout stride 72
#pragma unroll
        for (int i = 0; i < 4; i++) {
            const int fidx = t + i * 256;
            const int r  = fidx >> 4;
            const int c4 = (fidx & 15) << 2;
            float4 v = *reinterpret_cast<const float4*>(
                Vg + (long)(c * 64 + r) * Dsz + c4);
            uint4 u = {f2tf(v.x), f2tf(v.y), f2tf(v.z), f2tf(v.w)};
            *reinterpret_cast<uint4*>(&Vs[r * 72 + c4]) = u;
        }
        __syncthreads();   // Es + Vs visible to all warps

        // X += E_chunk @ V_chunk, K depth 64
#pragma unroll
        for (int ks = 0; ks < 8; ks++) {
            const int k8 = ks * 8;
            unsigned a[2][4];
#pragma unroll
            for (int mi = 0; mi < 2; mi++) {
                const int mb = wm + mi * 16;
                a[mi][0] = Es[(mb + g) * 68 + k8 + tg];
                a[mi][1] = Es[(mb + g + 8) * 68 + k8 + tg];
                a[mi][2] = Es[(mb + g) * 68 + k8 + tg + 4];
                a[mi][3] = Es[(mb + g + 8) * 68 + k8 + tg + 4];
            }
#pragma unroll
            for (int ni = 0; ni < 4; ni++) {
                const int nb = wn + ni * 8;
                unsigned b0 = Vs[(k8 + tg) * 72 + nb + g];
                unsigned b1 = Vs[(k8 + tg + 4) * 72 + nb + g];
#pragma unroll
                for (int mi = 0; mi < 2; mi++)
                    mma_tf32(xacc[mi][ni], a[mi][0], a[mi][1], a[mi][2],
                             a[mi][3], b0, b1);
            }
        }
    }

    // Row-sum reduction across warps
    const int sub = (warp >> 2) * 4 + tg;   // 0..7
#pragma unroll
    for (int mi = 0; mi < 2; mi++) {
        red[(wm + mi * 16 + g) * 9 + sub]     = rsum[mi * 2];
        red[(wm + mi * 16 + g + 8) * 9 + sub] = rsum[mi * 2 + 1];
    }
    __syncthreads();
    if (t < 128) {
        float s = 0.0f;
#pragma unroll
        for (int j = 0; j < 8; j++) s += red[t * 9 + j];
        g_S[(long)z * Ssz + row0 + t] = s;
        rinv[t] = 1.0f / s;
    }
    __syncthreads();

    // X epilogue with row scaling
    float* Xg = g_X + (long)b * Ssz * Dsz + h * DKsz;
#pragma unroll
    for (int mi = 0; mi < 2; mi++) {
#pragma unroll
        for (int ni = 0; ni < 4; ni++) {
            const int r0  = wm + mi * 16 + g;
            const int col = wn + ni * 8 + tg * 2;
            const float ri0 = rinv[r0];
            const float ri1 = rinv[r0 + 8];
            float2 v0 = {xacc[mi][ni][0] * ri0, xacc[mi][ni][1] * ri0};
            *reinterpret_cast<float2*>(Xg + (long)(row0 + r0) * Dsz + col) = v0;
            float2 v1 = {xacc[mi][ni][2] * ri1, xacc[mi][ni][3] * ri1};
            *reinterpret_cast<float2*>(Xg + (long)(row0 + r0 + 8) * Dsz + col) = v1;
        }
    }
}

// ---------------------------------------------------------------------------
// norm kernel: attn = E * (1/g_S[row]), in place, streaming.
// grid (Ssz, BHsz), 256 threads; 8 elements (2 float4) per thread.
// ---------------------------------------------------------------------------
__global__ void __launch_bounds__(256)
norm_kernel(float* __restrict__ attn) {
    const int row = blockIdx.x;
    const int z   = blockIdx.y;
    const int t   = threadIdx.x;

    const float ri = 1.0f / g_S[(long)z * Ssz + row];

    float* rp = attn + ((long)z * Ssz + row) * Ssz;
#pragma unroll
    for (int i = 0; i < 2; i++) {
        const int idx = (t + i * 256) * 4;
        float4 v = *reinterpret_cast<const float4*>(rp + idx);
        v.x *= ri; v.y *= ri; v.z *= ri; v.w *= ri;
        *reinterpret_cast<float4*>(rp + idx) = v;
    }
}

// ---------------------------------------------------------------------------
// Launch
// ---------------------------------------------------------------------------
extern "C" void kernel_launch(void* const* d_in, const int* in_sizes, int n_in,
                              void* d_out, int out_size) {
    const float* query = (const float*)d_in[0];
    const float* key   = (const float*)d_in[1];
    const float* value = (const float*)d_in[2];
    const int*   mask  = (const int*)d_in[3];
    const float* W_q   = (const float*)d_in[4];
    const float* W_k   = (const float*)d_in[5];
    const float* W_v   = (const float*)d_in[6];
    const float* W_o   = (const float*)d_in[7];

    float* out  = (float*)d_out;                        // (B,S,D)
    float* attn = out + (long)Bsz * Ssz * Dsz;          // (B,H,S,S)

    float *Q, *K, *V, *X;
    cudaGetSymbolAddress((void**)&Q, g_Q);
    cudaGetSymbolAddress((void**)&K, g_K);
    cudaGetSymbolAddress((void**)&V, g_V);
    cudaGetSymbolAddress((void**)&X, g_X);

    cudaFuncSetAttribute(fused_attn_kernel,
                         cudaFuncAttributeMaxDynamicSharedMemorySize, FA_SMEM);

    dim3 projGrid(Dsz / 64, (Bsz * Ssz) / 128);         // (16, 32)
    proj_kernel<<<projGrid, 256>>>(query, W_q, Q);
    proj_kernel<<<projGrid, 256>>>(key,   W_k, K);
    proj_kernel<<<projGrid, 256>>>(value, W_v, V);

    fused_attn_kernel<<<dim3(Ssz / 128, BHsz), 256, FA_SMEM>>>(mask, attn);
    norm_kernel<<<dim3(Ssz, BHsz), 256>>>(attn);        // E -> P in place

    proj_kernel<<<projGrid, 256>>>(X, W_o, out);
}

// round 12
// speedup vs baseline: 1.8625x; 1.0035x over previous
#include <cuda_runtime.h>
#include <math.h>

// Problem constants
#define Bsz 2
#define Ssz 2048
#define Dsz 1024
#define Hsz 16
#define DKsz 64
#define BHsz (Bsz * Hsz)

// Scratch (allocation-free rule: __device__ globals)
__device__ float g_Q[(long)Bsz * Ssz * Dsz];
__device__ float g_K[(long)Bsz * Ssz * Dsz];
__device__ float g_V[(long)Bsz * Ssz * Dsz];
__device__ float g_X[(long)Bsz * Ssz * Dsz];
// Per-row exp-sums (full row sum, computed by fused kernel)
__device__ float g_S[(long)BHsz * Ssz];

__device__ __forceinline__ unsigned f2tf(float f) {
    unsigned u;
    asm("cvt.rna.tf32.f32 %0, %1;" : "=r"(u) : "f"(f));
    return u;
}

__device__ __forceinline__ void mma_tf32(float c[4], unsigned a0, unsigned a1,
                                         unsigned a2, unsigned a3,
                                         unsigned b0, unsigned b1) {
    asm volatile(
        "mma.sync.aligned.m16n8k8.row.col.f32.tf32.tf32.f32 "
        "{%0,%1,%2,%3}, {%4,%5,%6,%7}, {%8,%9}, {%0,%1,%2,%3};"
        : "+f"(c[0]), "+f"(c[1]), "+f"(c[2]), "+f"(c[3])
        : "r"(a0), "r"(a1), "r"(a2), "r"(a3), "r"(b0), "r"(b1));
}

// ---------------------------------------------------------------------------
// tf32 tensor-core projection GEMM: C = A[M,K] @ B[K,N]
// Block tile 128x128, BK=32, 256 threads (8 warps, each 32x64 warp tile).
// grid (N/128, M/128).
// ---------------------------------------------------------------------------
__global__ void __launch_bounds__(256, 2)
proj_kernel(const float* __restrict__ A,
            const float* __restrict__ B,
            float* __restrict__ C) {
    __shared__ __align__(16) unsigned As[128][36];
    __shared__ __align__(16) unsigned Bs[32][136];

    const int t    = threadIdx.x;
    const int lane = t & 31;
    const int warp = t >> 5;
    const int wm   = (warp & 3) * 32;
    const int wn   = (warp >> 2) * 64;
    const int g    = lane >> 2;
    const int tg   = lane & 3;

    const int row0 = blockIdx.y * 128;
    const int col0 = blockIdx.x * 128;

    float c[2][8][4];
#pragma unroll
    for (int mi = 0; mi < 2; mi++)
#pragma unroll
        for (int ni = 0; ni < 8; ni++)
#pragma unroll
            for (int r = 0; r < 4; r++) c[mi][ni][r] = 0.0f;

    for (int k0 = 0; k0 < Dsz; k0 += 32) {
        // Stage A tile 128x32
#pragma unroll
        for (int i = 0; i < 4; i++) {
            const int fidx = t + i * 256;
            const int r  = fidx >> 3;
            const int c4 = (fidx & 7) << 2;
            float4 v = *reinterpret_cast<const float4*>(
                A + (long)(row0 + r) * Dsz + k0 + c4);
            uint4 u = {f2tf(v.x), f2tf(v.y), f2tf(v.z), f2tf(v.w)};
            *reinterpret_cast<uint4*>(&As[r][c4]) = u;
        }
        // Stage B tile 32x128
#pragma unroll
        for (int i = 0; i < 4; i++) {
            const int fidx = t + i * 256;
            const int r  = fidx >> 5;         // k 0..31
            const int c4 = (fidx & 31) << 2;  // n 0..124
            float4 v = *reinterpret_cast<const float4*>(
                B + (long)(k0 + r) * Dsz + col0 + c4);
            uint4 u = {f2tf(v.x), f2tf(v.y), f2tf(v.z), f2tf(v.w)};
            *reinterpret_cast<uint4*>(&Bs[r][c4]) = u;
        }
        __syncthreads();

#pragma unroll
        for (int ks = 0; ks < 4; ks++) {
            const int k8 = ks * 8;
            unsigned a[2][4];
#pragma unroll
            for (int mi = 0; mi < 2; mi++) {
                const int mb = wm + mi * 16;
                a[mi][0] = As[mb + g][k8 + tg];
                a[mi][1] = As[mb + g + 8][k8 + tg];
                a[mi][2] = As[mb + g][k8 + tg + 4];
                a[mi][3] = As[mb + g + 8][k8 + tg + 4];
            }
#pragma unroll
            for (int ni = 0; ni < 8; ni++) {
                const int nb = wn + ni * 8;
                unsigned b0 = Bs[k8 + tg][nb + g];
                unsigned b1 = Bs[k8 + tg + 4][nb + g];
#pragma unroll
                for (int mi = 0; mi < 2; mi++)
                    mma_tf32(c[mi][ni], a[mi][0], a[mi][1], a[mi][2], a[mi][3],
                             b0, b1);
            }
        }
        __syncthreads();
    }

#pragma unroll
    for (int mi = 0; mi < 2; mi++) {
#pragma unroll
        for (int ni = 0; ni < 8; ni++) {
            const int row = row0 + wm + mi * 16 + g;
            const int col = col0 + wn + ni * 8 + tg * 2;
            float2 v0 = {c[mi][ni][0], c[mi][ni][1]};
            *reinterpret_cast<float2*>(C + (long)row * Dsz + col) = v0;
            float2 v1 = {c[mi][ni][2], c[mi][ni][3]};
            *reinterpret_cast<float2*>(C + (long)(row + 8) * Dsz + col) = v1;
        }
    }
}

// ---------------------------------------------------------------------------
// Fused scores + exp + AV kernel (64 q-rows per block).
// Streams K/V in 64-col chunks: S = QK^T -> e = mask?exp(S/8-30):0 -> E gmem
// + tf32 smem -> X += E@V. Epilogue: rsum -> g_S, X *= 1/rsum.
// 8 warps: wm = (warp&3)*16, wn = (warp>>2)*32.
// Dynamic smem (u32 words): Qs 64*68, Ks 64*68, Vs 64*72, Es 64*68,
// red 64*9, rinv 64 -> 73216 B -> 3 CTAs/SM.
// grid (Ssz/64 = 32, BHsz = 32), 256 threads.
// ---------------------------------------------------------------------------
#define FA_SMEM 73216

__global__ void __launch_bounds__(256, 3)
fused_attn_kernel(const int* __restrict__ mask, float* __restrict__ E) {
    extern __shared__ __align__(16) unsigned sm[];
    unsigned* Qs   = sm;                               // [64][68]
    unsigned* Ks   = Qs + 64 * 68;                     // [64][68]
    unsigned* Vs   = Ks + 64 * 68;                     // [64][72]
    unsigned* Es   = Vs + 64 * 72;                     // [64][68]
    float*    red  = reinterpret_cast<float*>(Es + 64 * 68);   // [64][9]
    float*    rinv = red + 64 * 9;                     // [64]

    const int t    = threadIdx.x;
    const int lane = t & 31;
    const int warp = t >> 5;
    const int wm   = (warp & 3) * 16;
    const int wn   = (warp >> 2) * 32;
    const int g    = lane >> 2;
    const int tg   = lane & 3;

    const int z = blockIdx.y;
    const int b = z >> 4, h = z & 15;
    const int row0 = blockIdx.x * 64;

    const float* Qg = g_Q + (long)b * Ssz * Dsz + h * DKsz;
    const float* Kg = g_K + (long)b * Ssz * Dsz + h * DKsz;
    const float* Vg = g_V + (long)b * Ssz * Dsz + h * DKsz;
    float* Ez = E + (long)z * Ssz * Ssz;

    // Stage Q tile [64 x 64] as tf32 (once)
#pragma unroll
    for (int i = 0; i < 4; i++) {
        const int fidx = t + i * 256;
        const int r  = fidx >> 4;
        const int c4 = (fidx & 15) << 2;
        float4 v = *reinterpret_cast<const float4*>(
            Qg + (long)(row0 + r) * Dsz + c4);
        uint4 u = {f2tf(v.x), f2tf(v.y), f2tf(v.z), f2tf(v.w)};
        *reinterpret_cast<uint4*>(&Qs[r * 68 + c4]) = u;
    }

    float xacc[4][4];
#pragma unroll
    for (int ni = 0; ni < 4; ni++)
#pragma unroll
        for (int r = 0; r < 4; r++) xacc[ni][r] = 0.0f;
    float rsum[2] = {0.0f, 0.0f};

    const float SC = 0.125f * 1.44269504088896f;
    const float CB = -30.0f * 1.44269504088896f;

    for (int c = 0; c < Ssz / 64; c++) {
        __syncthreads();   // prior chunk's AV MMA done before buffers overwrite

        // Stage K chunk [64 n x 64 k], NT layout stride 68
#pragma unroll
        for (int i = 0; i < 4; i++) {
            const int fidx = t + i * 256;
            const int r  = fidx >> 4;
            const int c4 = (fidx & 15) << 2;
            float4 v = *reinterpret_cast<const float4*>(
                Kg + (long)(c * 64 + r) * Dsz + c4);
            uint4 u = {f2tf(v.x), f2tf(v.y), f2tf(v.z), f2tf(v.w)};
            *reinterpret_cast<uint4*>(&Ks[r * 68 + c4]) = u;
        }
        __syncthreads();

        // QK^T MMA: S chunk [64 x 64], K depth 64
        float sacc[4][4];
#pragma unroll
        for (int ni = 0; ni < 4; ni++)
#pragma unroll
            for (int r = 0; r < 4; r++) sacc[ni][r] = 0.0f;

#pragma unroll
        for (int ks = 0; ks < 8; ks++) {
            const int k8 = ks * 8;
            unsigned a0 = Qs[(wm + g) * 68 + k8 + tg];
            unsigned a1 = Qs[(wm + g + 8) * 68 + k8 + tg];
            unsigned a2 = Qs[(wm + g) * 68 + k8 + tg + 4];
            unsigned a3 = Qs[(wm + g + 8) * 68 + k8 + tg + 4];
#pragma unroll
            for (int ni = 0; ni < 4; ni++) {
                const int nb = wn + ni * 8;
                unsigned b0 = Ks[(nb + g) * 68 + k8 + tg];
                unsigned b1 = Ks[(nb + g) * 68 + k8 + tg + 4];
                mma_tf32(sacc[ni], a0, a1, a2, a3, b0, b1);
            }
        }

        // Epilogue: masked exp; write E gmem (fp32) + Es smem (tf32); rsum
#pragma unroll
        for (int ni = 0; ni < 4; ni++) {
            const int r0   = wm + g;
            const int col  = wn + ni * 8 + tg * 2;
            const int gcol = c * 64 + col;
            const long mbase = (long)b * Ssz * Ssz + gcol;

            int2 m0 = *reinterpret_cast<const int2*>(
                mask + mbase + (long)(row0 + r0) * Ssz);
            float e00 = (m0.x == 0) ? 0.0f : exp2f(fmaf(sacc[ni][0], SC, CB));
            float e01 = (m0.y == 0) ? 0.0f : exp2f(fmaf(sacc[ni][1], SC, CB));

            int2 m1 = *reinterpret_cast<const int2*>(
                mask + mbase + (long)(row0 + r0 + 8) * Ssz);
            float e10 = (m1.x == 0) ? 0.0f : exp2f(fmaf(sacc[ni][2], SC, CB));
            float e11 = (m1.y == 0) ? 0.0f : exp2f(fmaf(sacc[ni][3], SC, CB));

            float2 v0 = {e00, e01};
            *reinterpret_cast<float2*>(Ez + (long)(row0 + r0) * Ssz + gcol) = v0;
            float2 v1 = {e10, e11};
            *reinterpret_cast<float2*>(Ez + (long)(row0 + r0 + 8) * Ssz + gcol) = v1;

            Es[r0 * 68 + col]           = f2tf(e00);
            Es[r0 * 68 + col + 1]       = f2tf(e01);
            Es[(r0 + 8) * 68 + col]     = f2tf(e10);
            Es[(r0 + 8) * 68 + col + 1] = f2tf(e11);

            rsum[0] += e00 + e01;
            rsum[1] += e10 + e11;
        }

        // Stage V chunk [64 k x 64 n], NN layout stride 72
#pragma unroll
        for (int i = 0; i < 4; i++) {
            const int fidx = t + i * 256;
            const int r  = fidx >> 4;
            const int c4 = (fidx & 15) << 2;
            float4 v = *reinterpret_cast<const float4*>(
                Vg + (long)(c * 64 + r) * Dsz + c4);
            uint4 u = {f2tf(v.x), f2tf(v.y), f2tf(v.z), f2tf(v.w)};
            *reinterpret_cast<uint4*>(&Vs[r * 72 + c4]) = u;
        }
        __syncthreads();   // Es + Vs visible to all warps

        // X += E_chunk @ V_chunk, K depth 64
#pragma unroll
        for (int ks = 0; ks < 8; ks++) {
            const int k8 = ks * 8;
            unsigned a0 = Es[(wm + g) * 68 + k8 + tg];
            unsigned a1 = Es[(wm + g + 8) * 68 + k8 + tg];
            unsigned a2 = Es[(wm + g) * 68 + k8 + tg + 4];
            unsigned a3 = Es[(wm + g + 8) * 68 + k8 + tg + 4];
#pragma unroll
            for (int ni = 0; ni < 4; ni++) {
                const int nb = wn + ni * 8;
                unsigned b0 = Vs[(k8 + tg) * 72 + nb + g];
                unsigned b1 = Vs[(k8 + tg + 4) * 72 + nb + g];
                mma_tf32(xacc[ni], a0, a1, a2, a3, b0, b1);
            }
        }
    }

    // Row-sum reduction across warps
    const int sub = (warp >> 2) * 4 + tg;   // 0..7
    red[(wm + g) * 9 + sub]     = rsum[0];
    red[(wm + g + 8) * 9 + sub] = rsum[1];
    __syncthreads();
    if (t < 64) {
        float s = 0.0f;
#pragma unroll
        for (int j = 0; j < 8; j++) s += red[t * 9 + j];
        g_S[(long)z * Ssz + row0 + t] = s;
        rinv[t] = 1.0f / s;
    }
    __syncthreads();

    // X epilogue with row scaling
    float* Xg = g_X + (long)b * Ssz * Dsz + h * DKsz;
    const float ri0 = rinv[wm + g];
    const float ri1 = rinv[wm + g + 8];
#pragma unroll
    for (int ni = 0; ni < 4; ni++) {
        const int col = wn + ni * 8 + tg * 2;
        float2 v0 = {xacc[ni][0] * ri0, xacc[ni][1] * ri0};
        *reinterpret_cast<float2*>(
            Xg + (long)(row0 + wm + g) * Dsz + col) = v0;
        float2 v1 = {xacc[ni][2] * ri1, xacc[ni][3] * ri1};
        *reinterpret_cast<float2*>(
            Xg + (long)(row0 + wm + g + 8) * Dsz + col) = v1;
    }
}

// ---------------------------------------------------------------------------
// norm kernel: attn = E * (1/g_S[row]), in place, streaming.
// grid (Ssz, BHsz), 256 threads; 8 elements (2 float4) per thread.
// ---------------------------------------------------------------------------
__global__ void __launch_bounds__(256)
norm_kernel(float* __restrict__ attn) {
    const int row = blockIdx.x;
    const int z   = blockIdx.y;
    const int t   = threadIdx.x;

    const float ri = 1.0f / g_S[(long)z * Ssz + row];

    float* rp = attn + ((long)z * Ssz + row) * Ssz;
#pragma unroll
    for (int i = 0; i < 2; i++) {
        const int idx = (t + i * 256) * 4;
        float4 v = *reinterpret_cast<const float4*>(rp + idx);
        v.x *= ri; v.y *= ri; v.z *= ri; v.w *= ri;
        *reinterpret_cast<float4*>(rp + idx) = v;
    }
}

// ---------------------------------------------------------------------------
// Launch
// ---------------------------------------------------------------------------
extern "C" void kernel_launch(void* const* d_in, const int* in_sizes, int n_in,
                              void* d_out, int out_size) {
    const float* query = (const float*)d_in[0];
    const float* key   = (const float*)d_in[1];
    const float* value = (const float*)d_in[2];
    const int*   mask  = (const int*)d_in[3];
    const float* W_q   = (const float*)d_in[4];
    const float* W_k   = (const float*)d_in[5];
    const float* W_v   = (const float*)d_in[6];
    const float* W_o   = (const float*)d_in[7];

    float* out  = (float*)d_out;                        // (B,S,D)
    float* attn = out + (long)Bsz * Ssz * Dsz;          // (B,H,S,S)

    float *Q, *K, *V, *X;
    cudaGetSymbolAddress((void**)&Q, g_Q);
    cudaGetSymbolAddress((void**)&K, g_K);
    cudaGetSymbolAddress((void**)&V, g_V);
    cudaGetSymbolAddress((void**)&X, g_X);

    cudaFuncSetAttribute(fused_attn_kernel,
                         cudaFuncAttributeMaxDynamicSharedMemorySize, FA_SMEM);

    dim3 projGrid(Dsz / 128, (Bsz * Ssz) / 128);        // (8, 32)
    proj_kernel<<<projGrid, 256>>>(query, W_q, Q);
    proj_kernel<<<projGrid, 256>>>(key,   W_k, K);
    proj_kernel<<<projGrid, 256>>>(value, W_v, V);

    fused_attn_kernel<<<dim3(Ssz / 64, BHsz), 256, FA_SMEM>>>(mask, attn);
    norm_kernel<<<dim3(Ssz, BHsz), 256>>>(attn);        // E -> P in place

    proj_kernel<<<projGrid, 256>>>(X, W_o, out);
}

// round 14
// speedup vs baseline: 1.8839x; 1.0115x over previous
#include <cuda_runtime.h>
#include <math.h>

// Problem constants
#define Bsz 2
#define Ssz 2048
#define Dsz 1024
#define Hsz 16
#define DKsz 64
#define BHsz (Bsz * Hsz)

// Scratch (allocation-free rule: __device__ globals)
__device__ float g_Q[(long)Bsz * Ssz * Dsz];
__device__ float g_K[(long)Bsz * Ssz * Dsz];
__device__ float g_V[(long)Bsz * Ssz * Dsz];
__device__ float g_X[(long)Bsz * Ssz * Dsz];

__device__ __forceinline__ unsigned f2tf(float f) {
    unsigned u;
    asm("cvt.rna.tf32.f32 %0, %1;" : "=r"(u) : "f"(f));
    return u;
}

__device__ __forceinline__ void mma_tf32(float c[4], unsigned a0, unsigned a1,
                                         unsigned a2, unsigned a3,
                                         unsigned b0, unsigned b1) {
    asm volatile(
        "mma.sync.aligned.m16n8k8.row.col.f32.tf32.tf32.f32 "
        "{%0,%1,%2,%3}, {%4,%5,%6,%7}, {%8,%9}, {%0,%1,%2,%3};"
        : "+f"(c[0]), "+f"(c[1]), "+f"(c[2]), "+f"(c[3])
        : "r"(a0), "r"(a1), "r"(a2), "r"(a3), "r"(b0), "r"(b1));
}

// ---------------------------------------------------------------------------
// tf32 tensor-core projection GEMM: C = A[M,K] @ B[K,N]
// Block tile 128x128, BK=32, 256 threads (8 warps, each 32x64 warp tile).
// grid (N/128, M/128).
// ---------------------------------------------------------------------------
__global__ void __launch_bounds__(256, 2)
proj_kernel(const float* __restrict__ A,
            const float* __restrict__ B,
            float* __restrict__ C) {
    __shared__ __align__(16) unsigned As[128][36];
    __shared__ __align__(16) unsigned Bs[32][136];

    const int t    = threadIdx.x;
    const int lane = t & 31;
    const int warp = t >> 5;
    const int wm   = (warp & 3) * 32;
    const int wn   = (warp >> 2) * 64;
    const int g    = lane >> 2;
    const int tg   = lane & 3;

    const int row0 = blockIdx.y * 128;
    const int col0 = blockIdx.x * 128;

    float c[2][8][4];
#pragma unroll
    for (int mi = 0; mi < 2; mi++)
#pragma unroll
        for (int ni = 0; ni < 8; ni++)
#pragma unroll
            for (int r = 0; r < 4; r++) c[mi][ni][r] = 0.0f;

    for (int k0 = 0; k0 < Dsz; k0 += 32) {
        // Stage A tile 128x32
#pragma unroll
        for (int i = 0; i < 4; i++) {
            const int fidx = t + i * 256;
            const int r  = fidx >> 3;
            const int c4 = (fidx & 7) << 2;
            float4 v = *reinterpret_cast<const float4*>(
                A + (long)(row0 + r) * Dsz + k0 + c4);
            uint4 u = {f2tf(v.x), f2tf(v.y), f2tf(v.z), f2tf(v.w)};
            *reinterpret_cast<uint4*>(&As[r][c4]) = u;
        }
        // Stage B tile 32x128
#pragma unroll
        for (int i = 0; i < 4; i++) {
            const int fidx = t + i * 256;
            const int r  = fidx >> 5;         // k 0..31
            const int c4 = (fidx & 31) << 2;  // n 0..124
            float4 v = *reinterpret_cast<const float4*>(
                B + (long)(k0 + r) * Dsz + col0 + c4);
            uint4 u = {f2tf(v.x), f2tf(v.y), f2tf(v.z), f2tf(v.w)};
            *reinterpret_cast<uint4*>(&Bs[r][c4]) = u;
        }
        __syncthreads();

#pragma unroll
        for (int ks = 0; ks < 4; ks++) {
            const int k8 = ks * 8;
            unsigned a[2][4];
#pragma unroll
            for (int mi = 0; mi < 2; mi++) {
                const int mb = wm + mi * 16;
                a[mi][0] = As[mb + g][k8 + tg];
                a[mi][1] = As[mb + g + 8][k8 + tg];
                a[mi][2] = As[mb + g][k8 + tg + 4];
                a[mi][3] = As[mb + g + 8][k8 + tg + 4];
            }
#pragma unroll
            for (int ni = 0; ni < 8; ni++) {
                const int nb = wn + ni * 8;
                unsigned b0 = Bs[k8 + tg][nb + g];
                unsigned b1 = Bs[k8 + tg + 4][nb + g];
#pragma unroll
                for (int mi = 0; mi < 2; mi++)
                    mma_tf32(c[mi][ni], a[mi][0], a[mi][1], a[mi][2], a[mi][3],
                             b0, b1);
            }
        }
        __syncthreads();
    }

#pragma unroll
    for (int mi = 0; mi < 2; mi++) {
#pragma unroll
        for (int ni = 0; ni < 8; ni++) {
            const int row = row0 + wm + mi * 16 + g;
            const int col = col0 + wn + ni * 8 + tg * 2;
            float2 v0 = {c[mi][ni][0], c[mi][ni][1]};
            *reinterpret_cast<float2*>(C + (long)row * Dsz + col) = v0;
            float2 v1 = {c[mi][ni][2], c[mi][ni][3]};
            *reinterpret_cast<float2*>(C + (long)(row + 8) * Dsz + col) = v1;
        }
    }
}

// ---------------------------------------------------------------------------
// Fused scores + exp + AV + normalize kernel (128 q-rows per block).
// Per 64-col chunk: S = QK^T (MMA) -> e = mask?exp(S/8-30):0 -> write E gmem,
// tf32 copy smem -> X += E@V (MMA). After loop: rinv per row, X *= rinv,
// then rescale own E rows in place (L2-warm) -> normalized attn. No separate
// norm kernel.
// Dynamic smem: Qs 128*68, Ks 64*68, Vs 64*72, Es 128*68, red 128*9,
// rinv 128 -> 110592 B -> 2 CTAs/SM. grid (16, 32), 256 threads.
// ---------------------------------------------------------------------------
#define FA_SMEM 110592

__global__ void __launch_bounds__(256, 2)
fused_attn_kernel(const int* __restrict__ mask, float* __restrict__ E) {
    extern __shared__ __align__(16) unsigned sm[];
    unsigned* Qs   = sm;                              // [128][68]
    unsigned* Ks   = Qs + 128 * 68;                   // [64][68]
    unsigned* Vs   = Ks + 64 * 68;                    // [64][72]
    unsigned* Es   = Vs + 64 * 72;                    // [128][68]
    float*    red  = reinterpret_cast<float*>(Es + 128 * 68);  // [128][9]
    float*    rinv = red + 128 * 9;                   // [128]

    const int t    = threadIdx.x;
    const int lane = t & 31;
    const int warp = t >> 5;
    const int wm   = (warp & 3) * 32;
    const int wn   = (warp >> 2) * 32;
    const int g    = lane >> 2;
    const int tg   = lane & 3;

    const int z = blockIdx.y;
    const int b = z >> 4, h = z & 15;
    const int row0 = blockIdx.x * 128;

    const float* Qg = g_Q + (long)b * Ssz * Dsz + h * DKsz;
    const float* Kg = g_K + (long)b * Ssz * Dsz + h * DKsz;
    const float* Vg = g_V + (long)b * Ssz * Dsz + h * DKsz;
    float* Ez = E + (long)z * Ssz * Ssz;

    // Stage Q tile [128 x 64] as tf32 (once)
#pragma unroll
    for (int i = 0; i < 8; i++) {
        const int fidx = t + i * 256;
        const int r  = fidx >> 4;
        const int c4 = (fidx & 15) << 2;
        float4 v = *reinterpret_cast<const float4*>(
            Qg + (long)(row0 + r) * Dsz + c4);
        uint4 u = {f2tf(v.x), f2tf(v.y), f2tf(v.z), f2tf(v.w)};
        *reinterpret_cast<uint4*>(&Qs[r * 68 + c4]) = u;
    }

    float xacc[2][4][4];
#pragma unroll
    for (int mi = 0; mi < 2; mi++)
#pragma unroll
        for (int ni = 0; ni < 4; ni++)
#pragma unroll
            for (int r = 0; r < 4; r++) xacc[mi][ni][r] = 0.0f;
    float rsum[4] = {0.0f, 0.0f, 0.0f, 0.0f};

    const float SC = 0.125f * 1.44269504088896f;
    const float CB = -30.0f * 1.44269504088896f;

    for (int c = 0; c < Ssz / 64; c++) {
        __syncthreads();   // prior chunk's MMAs done before Ks/Vs/Es overwrite

        // Stage K chunk [64 n x 64 k], NT layout stride 68
#pragma unroll
        for (int i = 0; i < 4; i++) {
            const int fidx = t + i * 256;
            const int r  = fidx >> 4;
            const int c4 = (fidx & 15) << 2;
            float4 v = *reinterpret_cast<const float4*>(
                Kg + (long)(c * 64 + r) * Dsz + c4);
            uint4 u = {f2tf(v.x), f2tf(v.y), f2tf(v.z), f2tf(v.w)};
            *reinterpret_cast<uint4*>(&Ks[r * 68 + c4]) = u;
        }
        __syncthreads();

        // QK^T MMA: S chunk [128 x 64], K depth 64
        float sacc[2][4][4];
#pragma unroll
        for (int mi = 0; mi < 2; mi++)
#pragma unroll
            for (int ni = 0; ni < 4; ni++)
#pragma unroll
                for (int r = 0; r < 4; r++) sacc[mi][ni][r] = 0.0f;

#pragma unroll
        for (int ks = 0; ks < 8; ks++) {
            const int k8 = ks * 8;
            unsigned a[2][4];
#pragma unroll
            for (int mi = 0; mi < 2; mi++) {
                const int mb = wm + mi * 16;
                a[mi][0] = Qs[(mb + g) * 68 + k8 + tg];
                a[mi][1] = Qs[(mb + g + 8) * 68 + k8 + tg];
                a[mi][2] = Qs[(mb + g) * 68 + k8 + tg + 4];
                a[mi][3] = Qs[(mb + g + 8) * 68 + k8 + tg + 4];
            }
#pragma unroll
            for (int ni = 0; ni < 4; ni++) {
                const int nb = wn + ni * 8;
                unsigned b0 = Ks[(nb + g) * 68 + k8 + tg];
                unsigned b1 = Ks[(nb + g) * 68 + k8 + tg + 4];
#pragma unroll
                for (int mi = 0; mi < 2; mi++)
                    mma_tf32(sacc[mi][ni], a[mi][0], a[mi][1], a[mi][2],
                             a[mi][3], b0, b1);
            }
        }

        // Epilogue: masked exp; write E to gmem (fp32) + Es smem (tf32); rsum
#pragma unroll
        for (int mi = 0; mi < 2; mi++) {
#pragma unroll
            for (int ni = 0; ni < 4; ni++) {
                const int r0   = wm + mi * 16 + g;
                const int col  = wn + ni * 8 + tg * 2;
                const int gcol = c * 64 + col;
                const long mbase = (long)b * Ssz * Ssz + gcol;

                int2 m0 = *reinterpret_cast<const int2*>(
                    mask + mbase + (long)(row0 + r0) * Ssz);
                float e00 = (m0.x == 0) ? 0.0f : exp2f(fmaf(sacc[mi][ni][0], SC, CB));
                float e01 = (m0.y == 0) ? 0.0f : exp2f(fmaf(sacc[mi][ni][1], SC, CB));

                int2 m1 = *reinterpret_cast<const int2*>(
                    mask + mbase + (long)(row0 + r0 + 8) * Ssz);
                float e10 = (m1.x == 0) ? 0.0f : exp2f(fmaf(sacc[mi][ni][2], SC, CB));
                float e11 = (m1.y == 0) ? 0.0f : exp2f(fmaf(sacc[mi][ni][3], SC, CB));

                float2 v0 = {e00, e01};
                *reinterpret_cast<float2*>(
                    Ez + (long)(row0 + r0) * Ssz + gcol) = v0;
                float2 v1 = {e10, e11};
                *reinterpret_cast<float2*>(
                    Ez + (long)(row0 + r0 + 8) * Ssz + gcol) = v1;

                Es[r0 * 68 + col]           = f2tf(e00);
                Es[r0 * 68 + col + 1]       = f2tf(e01);
                Es[(r0 + 8) * 68 + col]     = f2tf(e10);
                Es[(r0 + 8) * 68 + col + 1] = f2tf(e11);

                rsum[mi * 2]     += e00 + e01;
                rsum[mi * 2 + 1] += e10 + e11;
            }
        }

        // Stage V chunk [64 k x 64 n], NN layout stride 72
#pragma unroll
        for (int i = 0; i < 4; i++) {
            const int fidx = t + i * 256;
            const int r  = fidx >> 4;
            const int c4 = (fidx & 15) << 2;
            float4 v = *reinterpret_cast<const float4*>(
                Vg + (long)(c * 64 + r) * Dsz + c4);
            uint4 u = {f2tf(v.x), f2tf(v.y), f2tf(v.z), f2tf(v.w)};
            *reinterpret_cast<uint4*>(&Vs[r * 72 + c4]) = u;
        }
        __syncthreads();   // Es + Vs visible to all warps

        // X += E_chunk @ V_chunk, K depth 64
#pragma unroll
        for (int ks = 0; ks < 8; ks++) {
            const int k8 = ks * 8;
            unsigned a[2][4];
#pragma unroll
            for (int mi = 0; mi < 2; mi++) {
                const int mb = wm + mi * 16;
                a[mi][0] = Es[(mb + g) * 68 + k8 + tg];
                a[mi][1] = Es[(mb + g + 8) * 68 + k8 + tg];
                a[mi][2] = Es[(mb + g) * 68 + k8 + tg + 4];
                a[mi][3] = Es[(mb + g + 8) * 68 + k8 + tg + 4];
            }
#pragma unroll
            for (int ni = 0; ni < 4; ni++) {
                const int nb = wn + ni * 8;
                unsigned b0 = Vs[(k8 + tg) * 72 + nb + g];
                unsigned b1 = Vs[(k8 + tg + 4) * 72 + nb + g];
#pragma unroll
                for (int mi = 0; mi < 2; mi++)
                    mma_tf32(xacc[mi][ni], a[mi][0], a[mi][1], a[mi][2],
                             a[mi][3], b0, b1);
            }
        }
    }

    // Row-sum reduction across warps
    const int sub = (warp >> 2) * 4 + tg;   // 0..7
#pragma unroll
    for (int mi = 0; mi < 2; mi++) {
        red[(wm + mi * 16 + g) * 9 + sub]     = rsum[mi * 2];
        red[(wm + mi * 16 + g + 8) * 9 + sub] = rsum[mi * 2 + 1];
    }
    __syncthreads();
    if (t < 128) {
        float s = 0.0f;
#pragma unroll
        for (int j = 0; j < 8; j++) s += red[t * 9 + j];
        rinv[t] = 1.0f / s;
    }
    __syncthreads();   // rinv ready; also fences block's E gmem writes

    // X epilogue with row scaling
    float* Xg = g_X + (long)b * Ssz * Dsz + h * DKsz;
#pragma unroll
    for (int mi = 0; mi < 2; mi++) {
#pragma unroll
        for (int ni = 0; ni < 4; ni++) {
            const int r0  = wm + mi * 16 + g;
            const int col = wn + ni * 8 + tg * 2;
            const float ri0 = rinv[r0];
            const float ri1 = rinv[r0 + 8];
            float2 v0 = {xacc[mi][ni][0] * ri0, xacc[mi][ni][1] * ri0};
            *reinterpret_cast<float2*>(Xg + (long)(row0 + r0) * Dsz + col) = v0;
            float2 v1 = {xacc[mi][ni][2] * ri1, xacc[mi][ni][3] * ri1};
            *reinterpret_cast<float2*>(Xg + (long)(row0 + r0 + 8) * Dsz + col) = v1;
        }
    }

    // Normalize this block's own E rows in place (data still L2-warm).
    // 128 rows x 2048 cols; per row: 512 float4s across 256 threads (2 each).
    for (int r = 0; r < 128; r++) {
        const float ri = rinv[r];
        float* rp = Ez + (long)(row0 + r) * Ssz;
#pragma unroll
        for (int i = 0; i < 2; i++) {
            const int idx = (t + i * 256) * 4;
            float4 v = *reinterpret_cast<const float4*>(rp + idx);
            v.x *= ri; v.y *= ri; v.z *= ri; v.w *= ri;
            *reinterpret_cast<float4*>(rp + idx) = v;
        }
    }
}

// ---------------------------------------------------------------------------
// Launch
// ---------------------------------------------------------------------------
extern "C" void kernel_launch(void* const* d_in, const int* in_sizes, int n_in,
                              void* d_out, int out_size) {
    const float* query = (const float*)d_in[0];
    const float* key   = (const float*)d_in[1];
    const float* value = (const float*)d_in[2];
    const int*   mask  = (const int*)d_in[3];
    const float* W_q   = (const float*)d_in[4];
    const float* W_k   = (const float*)d_in[5];
    const float* W_v   = (const float*)d_in[6];
    const float* W_o   = (const float*)d_in[7];

    float* out  = (float*)d_out;                        // (B,S,D)
    float* attn = out + (long)Bsz * Ssz * Dsz;          // (B,H,S,S)

    float *Q, *K, *V, *X;
    cudaGetSymbolAddress((void**)&Q, g_Q);
    cudaGetSymbolAddress((void**)&K, g_K);
    cudaGetSymbolAddress((void**)&V, g_V);
    cudaGetSymbolAddress((void**)&X, g_X);

    cudaFuncSetAttribute(fused_attn_kernel,
                         cudaFuncAttributeMaxDynamicSharedMemorySize, FA_SMEM);

    dim3 projGrid(Dsz / 128, (Bsz * Ssz) / 128);        // (8, 32)
    proj_kernel<<<projGrid, 256>>>(query, W_q, Q);
    proj_kernel<<<projGrid, 256>>>(key,   W_k, K);
    proj_kernel<<<projGrid, 256>>>(value, W_v, V);

    fused_attn_kernel<<<dim3(Ssz / 128, BHsz), 256, FA_SMEM>>>(mask, attn);

    proj_kernel<<<projGrid, 256>>>(X, W_o, out);
}

// round 16
// speedup vs baseline: 1.9613x; 1.0411x over previous
#include <cuda_runtime.h>
#include <math.h>

// Problem constants
#define Bsz 2
#define Ssz 2048
#define Dsz 1024
#define Hsz 16
#define DKsz 64
#define BHsz (Bsz * Hsz)

// Scratch (allocation-free rule: __device__ globals)
__device__ float g_Q[(long)Bsz * Ssz * Dsz];
__device__ float g_K[(long)Bsz * Ssz * Dsz];
__device__ float g_V[(long)Bsz * Ssz * Dsz];
__device__ float g_X[(long)Bsz * Ssz * Dsz];
// Per-row exp-sums (full row sum, computed by fused kernel)
__device__ float g_S[(long)BHsz * Ssz];

__device__ __forceinline__ unsigned f2tf(float f) {
    unsigned u;
    asm("cvt.rna.tf32.f32 %0, %1;" : "=r"(u) : "f"(f));
    return u;
}

__device__ __forceinline__ void mma_tf32(float c[4], unsigned a0, unsigned a1,
                                         unsigned a2, unsigned a3,
                                         unsigned b0, unsigned b1) {
    asm volatile(
        "mma.sync.aligned.m16n8k8.row.col.f32.tf32.tf32.f32 "
        "{%0,%1,%2,%3}, {%4,%5,%6,%7}, {%8,%9}, {%0,%1,%2,%3};"
        : "+f"(c[0]), "+f"(c[1]), "+f"(c[2]), "+f"(c[3])
        : "r"(a0), "r"(a1), "r"(a2), "r"(a3), "r"(b0), "r"(b1));
}

// ---------------------------------------------------------------------------
// tf32 tensor-core projection GEMM body: C = A[M,K] @ B[K,N]
// Block tile 128x128, BK=32, 256 threads (8 warps, each 32x64 warp tile).
// ---------------------------------------------------------------------------
__device__ __forceinline__ void proj_body(const float* __restrict__ A,
                                          const float* __restrict__ B,
                                          float* __restrict__ C) {
    __shared__ __align__(16) unsigned As[128][36];
    __shared__ __align__(16) unsigned Bs[32][136];

    const int t    = threadIdx.x;
    const int lane = t & 31;
    const int warp = t >> 5;
    const int wm   = (warp & 3) * 32;
    const int wn   = (warp >> 2) * 64;
    const int g    = lane >> 2;
    const int tg   = lane & 3;

    const int row0 = blockIdx.y * 128;
    const int col0 = blockIdx.x * 128;

    float c[2][8][4];
#pragma unroll
    for (int mi = 0; mi < 2; mi++)
#pragma unroll
        for (int ni = 0; ni < 8; ni++)
#pragma unroll
            for (int r = 0; r < 4; r++) c[mi][ni][r] = 0.0f;

    for (int k0 = 0; k0 < Dsz; k0 += 32) {
        // Stage A tile 128x32
#pragma unroll
        for (int i = 0; i < 4; i++) {
            const int fidx = t + i * 256;
            const int r  = fidx >> 3;
            const int c4 = (fidx & 7) << 2;
            float4 v = *reinterpret_cast<const float4*>(
                A + (long)(row0 + r) * Dsz + k0 + c4);
            uint4 u = {f2tf(v.x), f2tf(v.y), f2tf(v.z), f2tf(v.w)};
            *reinterpret_cast<uint4*>(&As[r][c4]) = u;
        }
        // Stage B tile 32x128
#pragma unroll
        for (int i = 0; i < 4; i++) {
            const int fidx = t + i * 256;
            const int r  = fidx >> 5;         // k 0..31
            const int c4 = (fidx & 31) << 2;  // n 0..124
            float4 v = *reinterpret_cast<const float4*>(
                B + (long)(k0 + r) * Dsz + col0 + c4);
            uint4 u = {f2tf(v.x), f2tf(v.y), f2tf(v.z), f2tf(v.w)};
            *reinterpret_cast<uint4*>(&Bs[r][c4]) = u;
        }
        __syncthreads();

#pragma unroll
        for (int ks = 0; ks < 4; ks++) {
            const int k8 = ks * 8;
            unsigned a[2][4];
#pragma unroll
            for (int mi = 0; mi < 2; mi++) {
                const int mb = wm + mi * 16;
                a[mi][0] = As[mb + g][k8 + tg];
                a[mi][1] = As[mb + g + 8][k8 + tg];
                a[mi][2] = As[mb + g][k8 + tg + 4];
                a[mi][3] = As[mb + g + 8][k8 + tg + 4];
            }
#pragma unroll
            for (int ni = 0; ni < 8; ni++) {
                const int nb = wn + ni * 8;
                unsigned b0 = Bs[k8 + tg][nb + g];
                unsigned b1 = Bs[k8 + tg + 4][nb + g];
#pragma unroll
                for (int mi = 0; mi < 2; mi++)
                    mma_tf32(c[mi][ni], a[mi][0], a[mi][1], a[mi][2], a[mi][3],
                             b0, b1);
            }
        }
        __syncthreads();
    }

#pragma unroll
    for (int mi = 0; mi < 2; mi++) {
#pragma unroll
        for (int ni = 0; ni < 8; ni++) {
            const int row = row0 + wm + mi * 16 + g;
            const int col = col0 + wn + ni * 8 + tg * 2;
            float2 v0 = {c[mi][ni][0], c[mi][ni][1]};
            *reinterpret_cast<float2*>(C + (long)row * Dsz + col) = v0;
            float2 v1 = {c[mi][ni][2], c[mi][ni][3]};
            *reinterpret_cast<float2*>(C + (long)(row + 8) * Dsz + col) = v1;
        }
    }
}

// Batched QKV projection: blockIdx.z selects (input, weight, output).
__global__ void __launch_bounds__(256, 2)
qkv_proj_kernel(const float* __restrict__ q_in, const float* __restrict__ Wq,
                const float* __restrict__ k_in, const float* __restrict__ Wk,
                const float* __restrict__ v_in, const float* __restrict__ Wv,
                float* __restrict__ Qo, float* __restrict__ Ko,
                float* __restrict__ Vo) {
    const int sel = blockIdx.z;
    const float* A = (sel == 0) ? q_in : (sel == 1) ? k_in : v_in;
    const float* B = (sel == 0) ? Wq   : (sel == 1) ? Wk   : Wv;
    float*       C = (sel == 0) ? Qo   : (sel == 1) ? Ko   : Vo;
    proj_body(A, B, C);
}

__global__ void __launch_bounds__(256, 2)
proj_kernel(const float* __restrict__ A,
            const float* __restrict__ B,
            float* __restrict__ C) {
    proj_body(A, B, C);
}

// ---------------------------------------------------------------------------
// Fused scores + exp + AV kernel (128 q-rows per block) — R10 geometry.
// Per 64-col chunk: S = QK^T (MMA) -> e = mask?exp(S/8-30):0 -> write E gmem,
// tf32 copy smem -> X += E@V (MMA). Epilogue: row sums -> g_S, X *= 1/rsum.
// Dynamic smem: Qs 128*68, Ks 64*68, Vs 64*72, Es 128*68, red 128*9,
// rinv 128 -> 110592 B -> 2 CTAs/SM. grid (16, 32), 256 threads.
// ---------------------------------------------------------------------------
#define FA_SMEM 110592

__global__ void __launch_bounds__(256, 2)
fused_attn_kernel(const int* __restrict__ mask, float* __restrict__ E) {
    extern __shared__ __align__(16) unsigned sm[];
    unsigned* Qs   = sm;                              // [128][68]
    unsigned* Ks   = Qs + 128 * 68;                   // [64][68]
    unsigned* Vs   = Ks + 64 * 68;                    // [64][72]
    unsigned* Es   = Vs + 64 * 72;                    // [128][68]
    float*    red  = reinterpret_cast<float*>(Es + 128 * 68);  // [128][9]
    float*    rinv = red + 128 * 9;                   // [128]

    const int t    = threadIdx.x;
    const int lane = t & 31;
    const int warp = t >> 5;
    const int wm   = (warp & 3) * 32;
    const int wn   = (warp >> 2) * 32;
    const int g    = lane >> 2;
    const int tg   = lane & 3;

    const int z = blockIdx.y;
    const int b = z >> 4, h = z & 15;
    const int row0 = blockIdx.x * 128;

    const float* Qg = g_Q + (long)b * Ssz * Dsz + h * DKsz;
    const float* Kg = g_K + (long)b * Ssz * Dsz + h * DKsz;
    const float* Vg = g_V + (long)b * Ssz * Dsz + h * DKsz;
    float* Ez = E + (long)z * Ssz * Ssz;

    // Stage Q tile [128 x 64] as tf32 (once)
#pragma unroll
    for (int i = 0; i < 8; i++) {
        const int fidx = t + i * 256;
        const int r  = fidx >> 4;
        const int c4 = (fidx & 15) << 2;
        float4 v = *reinterpret_cast<const float4*>(
            Qg + (long)(row0 + r) * Dsz + c4);
        uint4 u = {f2tf(v.x), f2tf(v.y), f2tf(v.z), f2tf(v.w)};
        *reinterpret_cast<uint4*>(&Qs[r * 68 + c4]) = u;
    }

    float xacc[2][4][4];
#pragma unroll
    for (int mi = 0; mi < 2; mi++)
#pragma unroll
        for (int ni = 0; ni < 4; ni++)
#pragma unroll
            for (int r = 0; r < 4; r++) xacc[mi][ni][r] = 0.0f;
    float rsum[4] = {0.0f, 0.0f, 0.0f, 0.0f};

    const float SC = 0.125f * 1.44269504088896f;
    const float CB = -30.0f * 1.44269504088896f;

    for (int c = 0; c < Ssz / 64; c++) {
        __syncthreads();   // prior chunk's MMAs done before Ks/Vs/Es overwrite

        // Stage K chunk [64 n x 64 k], NT layout stride 68
#pragma unroll
        for (int i = 0; i < 4; i++) {
            const int fidx = t + i * 256;
            const int r  = fidx >> 4;
            const int c4 = (fidx & 15) << 2;
            float4 v = *reinterpret_cast<const float4*>(
                Kg + (long)(c * 64 + r) * Dsz + c4);
            uint4 u = {f2tf(v.x), f2tf(v.y), f2tf(v.z), f2tf(v.w)};
            *reinterpret_cast<uint4*>(&Ks[r * 68 + c4]) = u;
        }
        __syncthreads();

        // QK^T MMA: S chunk [128 x 64], K depth 64
        float sacc[2][4][4];
#pragma unroll
        for (int mi = 0; mi < 2; mi++)
#pragma unroll
            for (int ni = 0; ni < 4; ni++)
#pragma unroll
                for (int r = 0; r < 4; r++) sacc[mi][ni][r] = 0.0f;

#pragma unroll
        for (int ks = 0; ks < 8; ks++) {
            const int k8 = ks * 8;
            unsigned a[2][4];
#pragma unroll
            for (int mi = 0; mi < 2; mi++) {
                const int mb = wm + mi * 16;
                a[mi][0] = Qs[(mb + g) * 68 + k8 + tg];
                a[mi][1] = Qs[(mb + g + 8) * 68 + k8 + tg];
                a[mi][2] = Qs[(mb + g) * 68 + k8 + tg + 4];
                a[mi][3] = Qs[(mb + g + 8) * 68 + k8 + tg + 4];
            }
#pragma unroll
            for (int ni = 0; ni < 4; ni++) {
                const int nb = wn + ni * 8;
                unsigned b0 = Ks[(nb + g) * 68 + k8 + tg];
                unsigned b1 = Ks[(nb + g) * 68 + k8 + tg + 4];
#pragma unroll
                for (int mi = 0; mi < 2; mi++)
                    mma_tf32(sacc[mi][ni], a[mi][0], a[mi][1], a[mi][2],
                             a[mi][3], b0, b1);
            }
        }

        // Epilogue: masked exp; write E to gmem (fp32) + Es smem (tf32); rsum
#pragma unroll
        for (int mi = 0; mi < 2; mi++) {
#pragma unroll
            for (int ni = 0; ni < 4; ni++) {
                const int r0   = wm + mi * 16 + g;
                const int col  = wn + ni * 8 + tg * 2;
                const int gcol = c * 64 + col;
                const long mbase = (long)b * Ssz * Ssz + gcol;

                int2 m0 = *reinterpret_cast<const int2*>(
                    mask + mbase + (long)(row0 + r0) * Ssz);
                float e00 = (m0.x == 0) ? 0.0f : exp2f(fmaf(sacc[mi][ni][0], SC, CB));
                float e01 = (m0.y == 0) ? 0.0f : exp2f(fmaf(sacc[mi][ni][1], SC, CB));

                int2 m1 = *reinterpret_cast<const int2*>(
                    mask + mbase + (long)(row0 + r0 + 8) * Ssz);
                float e10 = (m1.x == 0) ? 0.0f : exp2f(fmaf(sacc[mi][ni][2], SC, CB));
                float e11 = (m1.y == 0) ? 0.0f : exp2f(fmaf(sacc[mi][ni][3], SC, CB));

                float2 v0 = {e00, e01};
                *reinterpret_cast<float2*>(
                    Ez + (long)(row0 + r0) * Ssz + gcol) = v0;
                float2 v1 = {e10, e11};
                *reinterpret_cast<float2*>(
                    Ez + (long)(row0 + r0 + 8) * Ssz + gcol) = v1;

                Es[r0 * 68 + col]           = f2tf(e00);
                Es[r0 * 68 + col + 1]       = f2tf(e01);
                Es[(r0 + 8) * 68 + col]     = f2tf(e10);
                Es[(r0 + 8) * 68 + col + 1] = f2tf(e11);

                rsum[mi * 2]     += e00 + e01;
                rsum[mi * 2 + 1] += e10 + e11;
            }
        }

        // Stage V chunk [64 k x 64 n], NN layout stride 72
#pragma unroll
        for (int i = 0; i < 4; i++) {
            const int fidx = t + i * 256;
            const int r  = fidx >> 4;
            const int c4 = (fidx & 15) << 2;
            float4 v = *reinterpret_cast<const float4*>(
                Vg + (long)(c * 64 + r) * Dsz + c4);
            uint4 u = {f2tf(v.x), f2tf(v.y), f2tf(v.z), f2tf(v.w)};
            *reinterpret_cast<uint4*>(&Vs[r * 72 + c4]) = u;
        }
        __syncthreads();   // Es + Vs visible to all warps

        // X += E_chunk @ V_chunk, K depth 64
#pragma unroll
        for (int ks = 0; ks < 8; ks++) {
            const int k8 = ks * 8;
            unsigned a[2][4];
#pragma unroll
            for (int mi = 0; mi < 2; mi++) {
                const int mb = wm + mi * 16;
                a[mi][0] = Es[(mb + g) * 68 + k8 + tg];
                a[mi][1] = Es[(mb + g + 8) * 68 + k8 + tg];
                a[mi][2] = Es[(mb + g) * 68 + k8 + tg + 4];
                a[mi][3] = Es[(mb + g + 8) * 68 + k8 + tg + 4];
            }
#pragma unroll
            for (int ni = 0; ni < 4; ni++) {
                const int nb = wn + ni * 8;
                unsigned b0 = Vs[(k8 + tg) * 72 + nb + g];
                unsigned b1 = Vs[(k8 + tg + 4) * 72 + nb + g];
#pragma unroll
                for (int mi = 0; mi < 2; mi++)
                    mma_tf32(xacc[mi][ni], a[mi][0], a[mi][1], a[mi][2],
                             a[mi][3], b0, b1);
            }
        }
    }

    // Row-sum reduction across warps
    const int sub = (warp >> 2) * 4 + tg;   // 0..7
#pragma unroll
    for (int mi = 0; mi < 2; mi++) {
        red[(wm + mi * 16 + g) * 9 + sub]     = rsum[mi * 2];
        red[(wm + mi * 16 + g + 8) * 9 + sub] = rsum[mi * 2 + 1];
    }
    __syncthreads();
    if (t < 128) {
        float s = 0.0f;
#pragma unroll
        for (int j = 0; j < 8; j++) s += red[t * 9 + j];
        g_S[(long)z * Ssz + row0 + t] = s;
        rinv[t] = 1.0f / s;
    }
    __syncthreads();

    // X epilogue with row scaling
    float* Xg = g_X + (long)b * Ssz * Dsz + h * DKsz;
#pragma unroll
    for (int mi = 0; mi < 2; mi++) {
#pragma unroll
        for (int ni = 0; ni < 4; ni++) {
            const int r0  = wm + mi * 16 + g;
            const int col = wn + ni * 8 + tg * 2;
            const float ri0 = rinv[r0];
            const float ri1 = rinv[r0 + 8];
            float2 v0 = {xacc[mi][ni][0] * ri0, xacc[mi][ni][1] * ri0};
            *reinterpret_cast<float2*>(Xg + (long)(row0 + r0) * Dsz + col) = v0;
            float2 v1 = {xacc[mi][ni][2] * ri1, xacc[mi][ni][3] * ri1};
            *reinterpret_cast<float2*>(Xg + (long)(row0 + r0 + 8) * Dsz + col) = v1;
        }
    }
}

// ---------------------------------------------------------------------------
// norm kernel: attn = E * (1/g_S[row]), in place, streaming.
// grid (Ssz, BHsz), 256 threads; 8 elements (2 float4) per thread.
// ---------------------------------------------------------------------------
__global__ void __launch_bounds__(256)
norm_kernel(float* __restrict__ attn) {
    const int row = blockIdx.x;
    const int z   = blockIdx.y;
    const int t   = threadIdx.x;

    const float ri = 1.0f / g_S[(long)z * Ssz + row];

    float* rp = attn + ((long)z * Ssz + row) * Ssz;
#pragma unroll
    for (int i = 0; i < 2; i++) {
        const int idx = (t + i * 256) * 4;
        float4 v = *reinterpret_cast<const float4*>(rp + idx);
        v.x *= ri; v.y *= ri; v.z *= ri; v.w *= ri;
        *reinterpret_cast<float4*>(rp + idx) = v;
    }
}

// ---------------------------------------------------------------------------
// Launch
// ---------------------------------------------------------------------------
extern "C" void kernel_launch(void* const* d_in, const int* in_sizes, int n_in,
                              void* d_out, int out_size) {
    const float* query = (const float*)d_in[0];
    const float* key   = (const float*)d_in[1];
    const float* value = (const float*)d_in[2];
    const int*   mask  = (const int*)d_in[3];
    const float* W_q   = (const float*)d_in[4];
    const float* W_k   = (const float*)d_in[5];
    const float* W_v   = (const float*)d_in[6];
    const float* W_o   = (const float*)d_in[7];

    float* out  = (float*)d_out;                        // (B,S,D)
    float* attn = out + (long)Bsz * Ssz * Dsz;          // (B,H,S,S)

    float *Q, *K, *V, *X;
    cudaGetSymbolAddress((void**)&Q, g_Q);
    cudaGetSymbolAddress((void**)&K, g_K);
    cudaGetSymbolAddress((void**)&V, g_V);
    cudaGetSymbolAddress((void**)&X, g_X);

    cudaFuncSetAttribute(fused_attn_kernel,
                         cudaFuncAttributeMaxDynamicSharedMemorySize, FA_SMEM);

    dim3 projGrid(Dsz / 128, (Bsz * Ssz) / 128);        // (8, 32)
    qkv_proj_kernel<<<dim3(Dsz / 128, (Bsz * Ssz) / 128, 3), 256>>>(
        query, W_q, key, W_k, value, W_v, Q, K, V);

    fused_attn_kernel<<<dim3(Ssz / 128, BHsz), 256, FA_SMEM>>>(mask, attn);
    norm_kernel<<<dim3(Ssz, BHsz), 256>>>(attn);        // E -> P in place

    proj_kernel<<<projGrid, 256>>>(X, W_o, out);
}